// round 1
// baseline (speedup 1.0000x reference)
#include <cuda_runtime.h>
#include <math.h>

// Problem constants
#define B_SZ 2048
#define T_SZ 128
#define F_SZ 64
#define H_SZ 512
#define NG   2048   // 4*H

// ---------------------------------------------------------------------------
// State scratch (allocation-guard-legal __device__ globals).
// Ping-pong h buffers per layer (a step kernel reads h_prev while writing
// h_cur; in-place would race across blocks). c is updated strictly in-place
// by the owning thread, so no double buffer needed.
// ---------------------------------------------------------------------------
__device__ __align__(16) float g_h1[2][B_SZ * H_SZ];
__device__ __align__(16) float g_c1[B_SZ * H_SZ];
__device__ __align__(16) float g_h2[2][B_SZ * H_SZ];
__device__ __align__(16) float g_c2[B_SZ * H_SZ];

__global__ void init_state_kernel() {
    int idx = blockIdx.x * blockDim.x + threadIdx.x;
    if (idx < B_SZ * H_SZ) {
        // t=0 reads buffer index 1 (prev = (0&1)^1)
        g_h1[1][idx] = 0.f;
        g_h2[1][idx] = 0.f;
        g_c1[idx]    = 0.f;
        g_c2[idx]    = 0.f;
    }
}

// ---------------------------------------------------------------------------
// Accumulate C[4][BM=64][BN=64] += A[BM x K] * Bmat[K x 2048] where the 4
// output tiles are the 4 gate column-slices (g*512 + jb .. +64).
// Thread layout: tx = j within tile (2 cols: tx, tx+32), ty = 8-row group.
// ---------------------------------------------------------------------------
__device__ __forceinline__ void gemm_acc(
    const float* __restrict__ A, int lda,
    const float* __restrict__ Bmat, int K,
    int rb, int jb, int tx, int ty,
    float (*Asm)[68], float (*Bsm)[256],
    float acc[4][8][2])
{
    const int arow = threadIdx.x >> 2;          // 0..63
    const int kq   = (threadIdx.x & 3) << 2;    // 0,4,8,12
    const int krow = threadIdx.x >> 4;          // 0..15
    const int c4   = (threadIdx.x & 15) << 2;   // 0..60

    for (int k0 = 0; k0 < K; k0 += 16) {
        // A tile -> smem, k-major (Asm[k][row]) so inner loop reads broadcast
        float4 av = *reinterpret_cast<const float4*>(
            &A[(size_t)(rb + arow) * lda + k0 + kq]);
        Asm[kq + 0][arow] = av.x;
        Asm[kq + 1][arow] = av.y;
        Asm[kq + 2][arow] = av.z;
        Asm[kq + 3][arow] = av.w;

        // B tile: 16 k-rows x (4 gates x 64 j) columns
#pragma unroll
        for (int g = 0; g < 4; ++g) {
            *reinterpret_cast<float4*>(&Bsm[krow][g * 64 + c4]) =
                *reinterpret_cast<const float4*>(
                    &Bmat[(size_t)(k0 + krow) * NG + g * H_SZ + jb + c4]);
        }
        __syncthreads();

#pragma unroll
        for (int k = 0; k < 16; ++k) {
            float a[8];
#pragma unroll
            for (int r = 0; r < 8; ++r) a[r] = Asm[k][ty * 8 + r];
            float bb[4][2];
#pragma unroll
            for (int g = 0; g < 4; ++g) {
                bb[g][0] = Bsm[k][g * 64 + tx];
                bb[g][1] = Bsm[k][g * 64 + tx + 32];
            }
#pragma unroll
            for (int g = 0; g < 4; ++g)
#pragma unroll
                for (int r = 0; r < 8; ++r) {
                    acc[g][r][0] = fmaf(a[r], bb[g][0], acc[g][r][0]);
                    acc[g][r][1] = fmaf(a[r], bb[g][1], acc[g][r][1]);
                }
        }
        __syncthreads();
    }
}

// ---------------------------------------------------------------------------
// One LSTM timestep, fused: g = [A1 | h_prev] @ [W ; U] + b, then gate math.
// LAYER 1: A1 = x_t (K1=64), LAYER 2: A1 = h1_cur (K1=512).
// Grid: (H/64=8, B/64=32), 256 threads.
// ---------------------------------------------------------------------------
template <int LAYER>
__global__ void __launch_bounds__(256, 2)
lstm_step_kernel(const float* __restrict__ x,
                 const float* __restrict__ W,
                 const float* __restrict__ U,
                 const float* __restrict__ bias,
                 int t)
{
    __shared__ float Asm[16][68];
    __shared__ float Bsm[16][256];

    const int tx = threadIdx.x & 31;
    const int ty = threadIdx.x >> 5;
    const int jb = blockIdx.x * 64;
    const int rb = blockIdx.y * 64;
    const int cur = t & 1, prev = cur ^ 1;

    float acc[4][8][2];
#pragma unroll
    for (int g = 0; g < 4; ++g)
#pragma unroll
        for (int r = 0; r < 8; ++r) { acc[g][r][0] = 0.f; acc[g][r][1] = 0.f; }

    const float* A1;
    int          lda1, K1;
    const float* hprev;
    float*       cst;
    float*       hout;
    if (LAYER == 1) {
        A1 = x + (size_t)t * F_SZ;  lda1 = T_SZ * F_SZ;  K1 = F_SZ;
        hprev = g_h1[prev];  cst = g_c1;  hout = g_h1[cur];
    } else {
        A1 = g_h1[cur];      lda1 = H_SZ;          K1 = H_SZ;
        hprev = g_h2[prev];  cst = g_c2;  hout = g_h2[cur];
    }

    gemm_acc(A1,    lda1,  W, K1,    rb, jb, tx, ty, Asm, Bsm, acc);
    gemm_acc(hprev, H_SZ,  U, H_SZ,  rb, jb, tx, ty, Asm, Bsm, acc);

    // Epilogue: Keras gate order (i, f, c, o); recurrent act = sigmoid,
    // cell act = relu (applied to candidate AND cell output).
#pragma unroll
    for (int r = 0; r < 8; ++r) {
        const int row = rb + ty * 8 + r;
#pragma unroll
        for (int q = 0; q < 2; ++q) {
            const int j = jb + tx + q * 32;
            float gi = acc[0][r][q] + bias[j];
            float gf = acc[1][r][q] + bias[H_SZ + j];
            float gc = acc[2][r][q] + bias[2 * H_SZ + j];
            float go = acc[3][r][q] + bias[3 * H_SZ + j];
            gi = 1.f / (1.f + expf(-gi));
            gf = 1.f / (1.f + expf(-gf));
            go = 1.f / (1.f + expf(-go));
            gc = fmaxf(gc, 0.f);
            const size_t idx = (size_t)row * H_SZ + j;
            float cn = gf * cst[idx] + gi * gc;
            cst[idx]  = cn;
            hout[idx] = go * fmaxf(cn, 0.f);
        }
    }
}

// ---------------------------------------------------------------------------
// out[b] = h2_final[b,:] @ Wd + bd. One warp per row.
// ---------------------------------------------------------------------------
__global__ void dense_kernel(const float* __restrict__ Wd,
                             const float* __restrict__ bd,
                             float* __restrict__ out)
{
    const int row  = blockIdx.x * 8 + (threadIdx.x >> 5);
    const int lane = threadIdx.x & 31;
    const float* h2 = g_h2[(T_SZ - 1) & 1];  // buffer 1
    float s = 0.f;
#pragma unroll
    for (int j = lane; j < H_SZ; j += 32)
        s += h2[(size_t)row * H_SZ + j] * Wd[j];
#pragma unroll
    for (int o = 16; o; o >>= 1) s += __shfl_xor_sync(0xFFFFFFFFu, s, o);
    if (lane == 0) out[row] = s + bd[0];
}

// ---------------------------------------------------------------------------
extern "C" void kernel_launch(void* const* d_in, const int* in_sizes, int n_in,
                              void* d_out, int out_size)
{
    const float* x  = (const float*)d_in[0];
    const float* W1 = (const float*)d_in[1];
    const float* U1 = (const float*)d_in[2];
    const float* b1 = (const float*)d_in[3];
    const float* W2 = (const float*)d_in[4];
    const float* U2 = (const float*)d_in[5];
    const float* b2 = (const float*)d_in[6];
    const float* Wd = (const float*)d_in[7];
    const float* bd = (const float*)d_in[8];
    float* out = (float*)d_out;
    (void)in_sizes; (void)n_in; (void)out_size;

    init_state_kernel<<<(B_SZ * H_SZ + 255) / 256, 256>>>();

    dim3 grid(H_SZ / 64, B_SZ / 64);   // (8, 32)
    for (int t = 0; t < T_SZ; ++t) {
        lstm_step_kernel<1><<<grid, 256>>>(x, W1, U1, b1, t);
        lstm_step_kernel<2><<<grid, 256>>>(x, W2, U2, b2, t);
    }

    dense_kernel<<<B_SZ / 8, 256>>>(Wd, bd, out);
}

// round 3
// speedup vs baseline: 2.7298x; 2.7298x over previous
#include <cuda_runtime.h>
#include <cstdint>
#include <math.h>

#define B_SZ 2048
#define T_SZ 128
#define F_SZ 64
#define H_SZ 512
#define NSTG 3
#define KC   32
#define STAGE_BYTES (2 * 128 * 128)          // A(16KB) + B(16KB)
#define SMEM_DYN (NSTG * STAGE_BYTES)        // 96 KB

// ---------------------------------------------------------------------------
// Device scratch (allocation-guard-legal)
// ---------------------------------------------------------------------------
__device__ __align__(128) float g_h1[2][B_SZ * H_SZ];
__device__ __align__(128) float g_c1[B_SZ * H_SZ];
__device__ __align__(128) float g_h2[2][B_SZ * H_SZ];
__device__ __align__(128) float g_c2[B_SZ * H_SZ];
// Pre-transposed, gate-permuted weights, n-major: dst[n][k].
// permuted n -> gate g=(n>>4)&3, j=(n>>6)*16+(n&15); orig col = g*512 + j
__device__ __align__(128) float g_Wt1[2048 * 64];
__device__ __align__(128) float g_Ut1[2048 * 512];
__device__ __align__(128) float g_Wt2[2048 * 512];
__device__ __align__(128) float g_Ut2[2048 * 512];
__device__ __align__(128) float g_bp1[2048];
__device__ __align__(128) float g_bp2[2048];

// ---------------------------------------------------------------------------
// Helpers
// ---------------------------------------------------------------------------
__device__ __forceinline__ uint32_t smem_u32(const void* p) {
    uint32_t a;
    asm("{ .reg .u64 t; cvta.to.shared.u64 t, %1; cvt.u32.u64 %0, t; }" : "=r"(a) : "l"(p));
    return a;
}

#define CP_ASYNC16(dst, src) \
    asm volatile("cp.async.cg.shared.global [%0], [%1], 16;" :: "r"(dst), "l"(src) : "memory")
#define CP_ASYNC_COMMIT() asm volatile("cp.async.commit_group;" ::: "memory")
#define CP_ASYNC_WAIT(n)  asm volatile("cp.async.wait_group %0;" :: "n"(n) : "memory")

// Read f32 at logical (row, k = kchunk*4 + kq) from XOR-swizzled tile
__device__ __forceinline__ float lds_swz(uint32_t base, int r, int kchunk, int kq) {
    uint32_t addr = base + ((uint32_t)r << 7) + ((uint32_t)((kchunk ^ (r & 7))) << 4)
                  + ((uint32_t)kq << 2);
    float v;
    asm volatile("ld.shared.f32 %0, [%1];" : "=f"(v) : "r"(addr));
    return v;
}

__device__ __forceinline__ uint32_t to_tf32(float v) {
    uint32_t u;
    asm("cvt.rna.tf32.f32 %0, %1;" : "=r"(u) : "f"(v));
    return u;
}

#define MMA_TF32(c, a, b)                                                     \
    asm volatile("mma.sync.aligned.m16n8k8.row.col.f32.tf32.tf32.f32 "        \
        "{%0,%1,%2,%3}, {%4,%5,%6,%7}, {%8,%9}, {%0,%1,%2,%3};"               \
        : "+f"((c)[0]), "+f"((c)[1]), "+f"((c)[2]), "+f"((c)[3])              \
        : "r"((a)[0]), "r"((a)[1]), "r"((a)[2]), "r"((a)[3]),                 \
          "r"((b)[0]), "r"((b)[1]))

// ---------------------------------------------------------------------------
// Init / weight-prep kernels
// ---------------------------------------------------------------------------
__global__ void init_state_kernel() {
    int idx = blockIdx.x * blockDim.x + threadIdx.x;
    if (idx < B_SZ * H_SZ) {
        g_h1[1][idx] = 0.f; g_h2[1][idx] = 0.f;
        g_c1[idx] = 0.f;    g_c2[idx] = 0.f;
    }
}

__global__ void transpose_wu(const float* __restrict__ src, int K, int which) {
    float* dst = (which == 0) ? g_Wt1 : (which == 1) ? g_Ut1
               : (which == 2) ? g_Wt2 : g_Ut2;
    int idx = blockIdx.x * 256 + threadIdx.x;   // exact grid: 2048*K
    int n = idx / K, k = idx - n * K;
    int orig = ((n >> 4) & 3) * 512 + (n >> 6) * 16 + (n & 15);
    dst[idx] = src[(size_t)k * 2048 + orig];
}

__global__ void permute_bias(const float* __restrict__ b, int which) {
    float* dst = (which == 0) ? g_bp1 : g_bp2;
    int n = blockIdx.x * 256 + threadIdx.x;
    dst[n] = b[((n >> 4) & 3) * 512 + (n >> 6) * 16 + (n & 15)];
}

// ---------------------------------------------------------------------------
// Stage loader: A[128 x 32] + B[128 x 32], 128B rows, XOR-swizzled 16B chunks
// ---------------------------------------------------------------------------
__device__ __forceinline__ void load_chunk(
    int c, uint32_t stBase, int tid, int NC1,
    const float* __restrict__ A1, size_t sA1, const float* __restrict__ A2,
    const float* __restrict__ B1, int K1, const float* __restrict__ B2,
    int rb, int cb)
{
    const float* Asrc; size_t sA; const float* Bsrc; int BK; int kloc;
    if (c < NC1) { Asrc = A1; sA = sA1;  Bsrc = B1; BK = K1;   kloc = c * KC; }
    else         { Asrc = A2; sA = H_SZ; Bsrc = B2; BK = H_SZ; kloc = (c - NC1) * KC; }

    const int r  = tid >> 1;            // 0..127
    const int cq = (tid & 1) * 4;       // chunk 0..3 or 4..7
    const uint32_t aS = stBase;
    const uint32_t bS = stBase + 16384;

    const float* ag = Asrc + (size_t)(rb + r) * sA + kloc + cq * 4;
    const float* bg = Bsrc + (size_t)(cb + r) * BK + kloc + cq * 4;
    const uint32_t rowoff = (uint32_t)r << 7;
#pragma unroll
    for (int q = 0; q < 4; ++q) {
        uint32_t sw = (uint32_t)((cq + q) ^ (r & 7)) << 4;
        CP_ASYNC16(aS + rowoff + sw, ag + q * 4);
        CP_ASYNC16(bS + rowoff + sw, bg + q * 4);
    }
    CP_ASYNC_COMMIT();
}

// ---------------------------------------------------------------------------
// Fused LSTM step: tf32 mma.sync GEMM [128x128 tile, K = K1+512] + gate math
// Grid (16 N-tiles, 16 M-tiles), 256 threads (8 warps of 32x64).
// ---------------------------------------------------------------------------
template <int LAYER>
__global__ void __launch_bounds__(256, 2)
lstm_step_mma(const float* __restrict__ x, int t)
{
    extern __shared__ char dynraw[];
    __shared__ float s_bias[128];

    const int tid  = threadIdx.x;
    const int lane = tid & 31;
    const int warp = tid >> 5;
    const int wm   = warp >> 1;          // 0..3  (M)
    const int wn   = warp & 1;           // 0..1  (N)
    const int cur = t & 1, prev = cur ^ 1;
    const int rb = blockIdx.y * 128;
    const int cb = blockIdx.x * 128;

    constexpr int K1  = (LAYER == 1) ? F_SZ : H_SZ;
    constexpr int NC1 = K1 / KC;
    constexpr int NC  = NC1 + H_SZ / KC;

    const float *A1, *A2, *B1, *B2, *bp; float *cst, *hout; size_t sA1;
    if (LAYER == 1) {
        A1 = x + (size_t)t * F_SZ; sA1 = (size_t)T_SZ * F_SZ;
        A2 = g_h1[prev]; B1 = g_Wt1; B2 = g_Ut1; bp = g_bp1;
        cst = g_c1; hout = g_h1[cur];
    } else {
        A1 = g_h1[cur]; sA1 = H_SZ;
        A2 = g_h2[prev]; B1 = g_Wt2; B2 = g_Ut2; bp = g_bp2;
        cst = g_c2; hout = g_h2[cur];
    }

    const uint32_t base = smem_u32(dynraw);
    if (tid < 128) s_bias[tid] = bp[cb + tid];

    float acc[2][8][4];
#pragma unroll
    for (int mi = 0; mi < 2; ++mi)
#pragma unroll
        for (int nf = 0; nf < 8; ++nf)
#pragma unroll
            for (int e = 0; e < 4; ++e) acc[mi][nf][e] = 0.f;

    // Prologue
#pragma unroll
    for (int c = 0; c < NSTG; ++c)
        load_chunk(c, base + c * STAGE_BYTES, tid, NC1, A1, sA1, A2, B1, K1, B2, rb, cb);

    const int rA  = lane >> 2;          // fragment row/col within 8
    const int kq  = lane & 3;

    for (int c = 0; c < NC; ++c) {
        const int s = (c % NSTG);
        const uint32_t aS = base + s * STAGE_BYTES;
        const uint32_t bS = aS + 16384;
        CP_ASYNC_WAIT(NSTG - 1);
        __syncthreads();

#pragma unroll
        for (int ks = 0; ks < 4; ++ks) {
            const int ch0 = ks * 2;      // k-chunk of k..k+3
            uint32_t afr[2][4];
#pragma unroll
            for (int mi = 0; mi < 2; ++mi) {
                const int r0 = wm * 32 + mi * 16 + rA;
                afr[mi][0] = to_tf32(lds_swz(aS, r0,     ch0,     kq));
                afr[mi][1] = to_tf32(lds_swz(aS, r0 + 8, ch0,     kq));
                afr[mi][2] = to_tf32(lds_swz(aS, r0,     ch0 + 1, kq));
                afr[mi][3] = to_tf32(lds_swz(aS, r0 + 8, ch0 + 1, kq));
            }
            uint32_t bfr[8][2];
#pragma unroll
            for (int nf = 0; nf < 8; ++nf) {
                const int n0 = wn * 64 + nf * 8 + rA;
                bfr[nf][0] = to_tf32(lds_swz(bS, n0, ch0,     kq));
                bfr[nf][1] = to_tf32(lds_swz(bS, n0, ch0 + 1, kq));
            }
#pragma unroll
            for (int mi = 0; mi < 2; ++mi)
#pragma unroll
                for (int nf = 0; nf < 8; ++nf)
                    MMA_TF32(acc[mi][nf], afr[mi], bfr[nf]);
        }
        __syncthreads();
        if (c + NSTG < NC)
            load_chunk(c + NSTG, aS, tid, NC1, A1, sA1, A2, B1, K1, B2, rb, cb);
    }

    // ---- Fused LSTM epilogue ---------------------------------------------
    // Warp cols (wn*64 .. +63) = 4 gates x 16 j. Thread cell (mi, ri, h):
    //   row = rb + wm*32 + mi*16 + rA + ri*8
    //   j_local = h*8 + kq*2 + e (e=0,1), gate g value = acc[mi][g*2+h][ri*2+e]
    //   global j = (cb + wn*64)/64*16 + j_local = (bx*2+wn)*16 + j_local
    const int jgbase = (blockIdx.x * 2 + wn) * 16;
#pragma unroll
    for (int mi = 0; mi < 2; ++mi) {
#pragma unroll
        for (int ri = 0; ri < 2; ++ri) {
            const int row = rb + wm * 32 + mi * 16 + rA + ri * 8;
#pragma unroll
            for (int h = 0; h < 2; ++h) {
                const int jl = h * 8 + kq * 2;
                const size_t gidx = (size_t)row * H_SZ + jgbase + jl;
                float2 cold = *reinterpret_cast<const float2*>(&cst[gidx]);
                float cn2[2], hn2[2];
#pragma unroll
                for (int e = 0; e < 2; ++e) {
                    const int bofs = wn * 64 + h * 8 + kq * 2 + e;   // within s_bias, gate 0
                    float gi = acc[mi][0 * 2 + h][ri * 2 + e] + s_bias[bofs];
                    float gf = acc[mi][1 * 2 + h][ri * 2 + e] + s_bias[bofs + 16];
                    float gc = acc[mi][2 * 2 + h][ri * 2 + e] + s_bias[bofs + 32];
                    float go = acc[mi][3 * 2 + h][ri * 2 + e] + s_bias[bofs + 48];
                    gi = 1.f / (1.f + __expf(-gi));
                    gf = 1.f / (1.f + __expf(-gf));
                    go = 1.f / (1.f + __expf(-go));
                    gc = fmaxf(gc, 0.f);
                    float co = (e == 0) ? cold.x : cold.y;
                    float cn = gf * co + gi * gc;
                    cn2[e] = cn;
                    hn2[e] = go * fmaxf(cn, 0.f);
                }
                *reinterpret_cast<float2*>(&cst[gidx])  = make_float2(cn2[0], cn2[1]);
                *reinterpret_cast<float2*>(&hout[gidx]) = make_float2(hn2[0], hn2[1]);
            }
        }
    }
}

// ---------------------------------------------------------------------------
// Final dense: out[b] = h2[b,:] @ Wd + bd
// ---------------------------------------------------------------------------
__global__ void dense_kernel(const float* __restrict__ Wd,
                             const float* __restrict__ bd,
                             float* __restrict__ out)
{
    const int row  = blockIdx.x * 8 + (threadIdx.x >> 5);
    const int lane = threadIdx.x & 31;
    const float* h2 = g_h2[(T_SZ - 1) & 1];
    float s = 0.f;
#pragma unroll
    for (int j = lane; j < H_SZ; j += 32)
        s += h2[(size_t)row * H_SZ + j] * Wd[j];
#pragma unroll
    for (int o = 16; o; o >>= 1) s += __shfl_xor_sync(0xFFFFFFFFu, s, o);
    if (lane == 0) out[row] = s + bd[0];
}

// ---------------------------------------------------------------------------
extern "C" void kernel_launch(void* const* d_in, const int* in_sizes, int n_in,
                              void* d_out, int out_size)
{
    const float* x  = (const float*)d_in[0];
    const float* W1 = (const float*)d_in[1];
    const float* U1 = (const float*)d_in[2];
    const float* b1 = (const float*)d_in[3];
    const float* W2 = (const float*)d_in[4];
    const float* U2 = (const float*)d_in[5];
    const float* b2 = (const float*)d_in[6];
    const float* Wd = (const float*)d_in[7];
    const float* bd = (const float*)d_in[8];
    float* out = (float*)d_out;
    (void)in_sizes; (void)n_in; (void)out_size;

    cudaFuncSetAttribute(lstm_step_mma<1>,
                         cudaFuncAttributeMaxDynamicSharedMemorySize, SMEM_DYN);
    cudaFuncSetAttribute(lstm_step_mma<2>,
                         cudaFuncAttributeMaxDynamicSharedMemorySize, SMEM_DYN);

    init_state_kernel<<<(B_SZ * H_SZ + 255) / 256, 256>>>();
    transpose_wu<<<2048 * 64 / 256, 256>>>(W1, 64, 0);
    transpose_wu<<<2048 * 512 / 256, 256>>>(U1, 512, 1);
    transpose_wu<<<2048 * 512 / 256, 256>>>(W2, 512, 2);
    transpose_wu<<<2048 * 512 / 256, 256>>>(U2, 512, 3);
    permute_bias<<<8, 256>>>(b1, 0);
    permute_bias<<<8, 256>>>(b2, 1);

    dim3 grid(16, 16);   // (N tiles, M tiles)
    for (int t = 0; t < T_SZ; ++t) {
        lstm_step_mma<1><<<grid, 256, SMEM_DYN>>>(x, t);
        lstm_step_mma<2><<<grid, 256, SMEM_DYN>>>(x, t);
    }

    dense_kernel<<<B_SZ / 8, 256>>>(Wd, bd, out);
}

// round 4
// speedup vs baseline: 3.1091x; 1.1389x over previous
#include <cuda_runtime.h>
#include <cstdint>
#include <math.h>

#define B_SZ 2048
#define T_SZ 128
#define F_SZ 64
#define H_SZ 512
#define NSTG 3
#define KC   32
#define STAGE_BYTES (2 * 128 * 128)          // A(16KB) + B(16KB)
#define SMEM_DYN (NSTG * STAGE_BYTES)        // 96 KB

// ---------------------------------------------------------------------------
// Device scratch (allocation-guard-legal). h buffers hold tf32-rounded values
// (they only feed MMAs, which round anyway, and the final dense).
// ---------------------------------------------------------------------------
__device__ __align__(128) float g_h1[2][B_SZ * H_SZ];
__device__ __align__(128) float g_c1[B_SZ * H_SZ];
__device__ __align__(128) float g_h2[2][B_SZ * H_SZ];
__device__ __align__(128) float g_c2[B_SZ * H_SZ];
__device__ __align__(128) float g_x32[B_SZ * T_SZ * F_SZ];   // tf32-rounded x
// Pre-transposed, gate-permuted, tf32-rounded weights, n-major: dst[n][k].
// permuted n -> gate g=(n>>4)&3, j=(n>>6)*16+(n&15); orig col = g*512 + j
__device__ __align__(128) float g_Wt1[2048 * 64];
__device__ __align__(128) float g_Ut1[2048 * 512];
__device__ __align__(128) float g_Wt2[2048 * 512];
__device__ __align__(128) float g_Ut2[2048 * 512];
__device__ __align__(128) float g_bp1[2048];
__device__ __align__(128) float g_bp2[2048];

// ---------------------------------------------------------------------------
// Helpers
// ---------------------------------------------------------------------------
__device__ __forceinline__ uint32_t smem_u32(const void* p) {
    uint32_t a;
    asm("{ .reg .u64 t; cvta.to.shared.u64 t, %1; cvt.u32.u64 %0, t; }" : "=r"(a) : "l"(p));
    return a;
}

#define CP_ASYNC16(dst, src) \
    asm volatile("cp.async.cg.shared.global [%0], [%1], 16;" :: "r"(dst), "l"(src) : "memory")
#define CP_ASYNC_COMMIT() asm volatile("cp.async.commit_group;" ::: "memory")
#define CP_ASYNC_WAIT(n)  asm volatile("cp.async.wait_group %0;" :: "n"(n) : "memory")

__device__ __forceinline__ float to_tf32f(float v) {
    uint32_t u;
    asm("cvt.rna.tf32.f32 %0, %1;" : "=r"(u) : "f"(v));
    return __uint_as_float(u);
}

#define LDSM4(r0, r1, r2, r3, addr)                                           \
    asm volatile("ldmatrix.sync.aligned.m8n8.x4.shared.b16 {%0,%1,%2,%3}, [%4];" \
        : "=r"(r0), "=r"(r1), "=r"(r2), "=r"(r3) : "r"(addr))

#define MMA_TF32(c, a, b)                                                     \
    asm volatile("mma.sync.aligned.m16n8k8.row.col.f32.tf32.tf32.f32 "        \
        "{%0,%1,%2,%3}, {%4,%5,%6,%7}, {%8,%9}, {%0,%1,%2,%3};"               \
        : "+f"((c)[0]), "+f"((c)[1]), "+f"((c)[2]), "+f"((c)[3])              \
        : "r"((a)[0]), "r"((a)[1]), "r"((a)[2]), "r"((a)[3]),                 \
          "r"((b)[0]), "r"((b)[1]))

// ---------------------------------------------------------------------------
// Init / weight-prep kernels (all pre-round to tf32)
// ---------------------------------------------------------------------------
__global__ void init_state_kernel() {
    int idx = blockIdx.x * blockDim.x + threadIdx.x;
    if (idx < B_SZ * H_SZ) {
        g_h1[1][idx] = 0.f; g_h2[1][idx] = 0.f;
        g_c1[idx] = 0.f;    g_c2[idx] = 0.f;
    }
}

__global__ void convert_x(const float* __restrict__ x) {
    int idx = blockIdx.x * 256 + threadIdx.x;   // exact grid
    g_x32[idx] = to_tf32f(x[idx]);
}

__global__ void transpose_wu(const float* __restrict__ src, int K, int which) {
    float* dst = (which == 0) ? g_Wt1 : (which == 1) ? g_Ut1
               : (which == 2) ? g_Wt2 : g_Ut2;
    int idx = blockIdx.x * 256 + threadIdx.x;   // exact grid: 2048*K
    int n = idx / K, k = idx - n * K;
    int orig = ((n >> 4) & 3) * 512 + (n >> 6) * 16 + (n & 15);
    dst[idx] = to_tf32f(src[(size_t)k * 2048 + orig]);
}

__global__ void permute_bias(const float* __restrict__ b, int which) {
    float* dst = (which == 0) ? g_bp1 : g_bp2;
    int n = blockIdx.x * 256 + threadIdx.x;
    dst[n] = b[((n >> 4) & 3) * 512 + (n >> 6) * 16 + (n & 15)];
}

// ---------------------------------------------------------------------------
// Stage loader: A[128 x 32] + B[128 x 32], 128B rows, XOR-swizzled 16B chunks
// ---------------------------------------------------------------------------
__device__ __forceinline__ void load_chunk(
    int c, uint32_t stBase, int tid, int NC1,
    const float* __restrict__ A1, size_t sA1, const float* __restrict__ A2,
    const float* __restrict__ B1, int K1, const float* __restrict__ B2,
    int rb, int cb)
{
    const float* Asrc; size_t sA; const float* Bsrc; int BK; int kloc;
    if (c < NC1) { Asrc = A1; sA = sA1;  Bsrc = B1; BK = K1;   kloc = c * KC; }
    else         { Asrc = A2; sA = H_SZ; Bsrc = B2; BK = H_SZ; kloc = (c - NC1) * KC; }

    const int r  = tid >> 1;            // 0..127
    const int cq = (tid & 1) * 4;       // chunk 0..3 or 4..7
    const uint32_t aS = stBase;
    const uint32_t bS = stBase + 16384;

    const float* ag = Asrc + (size_t)(rb + r) * sA + kloc + cq * 4;
    const float* bg = Bsrc + (size_t)(cb + r) * BK + kloc + cq * 4;
    const uint32_t rowoff = (uint32_t)r << 7;
#pragma unroll
    for (int q = 0; q < 4; ++q) {
        uint32_t sw = (uint32_t)((cq + q) ^ (r & 7)) << 4;
        CP_ASYNC16(aS + rowoff + sw, ag + q * 4);
        CP_ASYNC16(bS + rowoff + sw, bg + q * 4);
    }
    CP_ASYNC_COMMIT();
}

// ---------------------------------------------------------------------------
// Fused LSTM step: tf32 mma.sync GEMM [128x128 tile, K = K1+512] + gate math
// Grid (16 N-tiles, 16 M-tiles), 256 threads (8 warps of 32x64).
// Fragments loaded via ldmatrix.x4 (data pre-rounded to tf32 in gmem).
// ---------------------------------------------------------------------------
template <int LAYER>
__global__ void __launch_bounds__(256, 2)
lstm_step_mma(int t)
{
    extern __shared__ char dynraw[];
    __shared__ float s_bias[128];

    const int tid  = threadIdx.x;
    const int lane = tid & 31;
    const int warp = tid >> 5;
    const int wm   = warp >> 1;          // 0..3  (M)
    const int wn   = warp & 1;           // 0..1  (N)
    const int cur = t & 1, prev = cur ^ 1;
    const int rb = blockIdx.y * 128;
    const int cb = blockIdx.x * 128;

    constexpr int K1  = (LAYER == 1) ? F_SZ : H_SZ;
    constexpr int NC1 = K1 / KC;
    constexpr int NC  = NC1 + H_SZ / KC;

    const float *A1, *A2, *B1, *B2, *bp; float *cst, *hout; size_t sA1;
    if (LAYER == 1) {
        A1 = g_x32 + (size_t)t * F_SZ; sA1 = (size_t)T_SZ * F_SZ;
        A2 = g_h1[prev]; B1 = g_Wt1; B2 = g_Ut1; bp = g_bp1;
        cst = g_c1; hout = g_h1[cur];
    } else {
        A1 = g_h1[cur]; sA1 = H_SZ;
        A2 = g_h2[prev]; B1 = g_Wt2; B2 = g_Ut2; bp = g_bp2;
        cst = g_c2; hout = g_h2[cur];
    }

    const uint32_t base = smem_u32(dynraw);
    if (tid < 128) s_bias[tid] = bp[cb + tid];

    float acc[2][8][4];
#pragma unroll
    for (int mi = 0; mi < 2; ++mi)
#pragma unroll
        for (int nf = 0; nf < 8; ++nf)
#pragma unroll
            for (int e = 0; e < 4; ++e) acc[mi][nf][e] = 0.f;

    // Prologue
#pragma unroll
    for (int c = 0; c < NSTG; ++c)
        load_chunk(c, base + c * STAGE_BYTES, tid, NC1, A1, sA1, A2, B1, K1, B2, rb, cb);

    // ldmatrix per-thread invariants
    const int lrow = lane & 7;
    const int lm   = lane >> 3;           // matrix id 0..3
    // A: matrices (rows +0/+8) x (chunk +0/+1)
    const uint32_t arow = (uint32_t)(wm * 32 + (lm & 1) * 8 + lrow);
    const int      ach  = lm >> 1;
    // B: matrices (n +0/+8) x (chunk +0/+1)
    const uint32_t bnrow0 = (uint32_t)(wn * 64 + (lm >> 1) * 8 + lrow);
    const int      bch    = lm & 1;

    for (int c = 0; c < NC; ++c) {
        const int s = (c % NSTG);
        const uint32_t aS = base + s * STAGE_BYTES;
        const uint32_t bS = aS + 16384;
        CP_ASYNC_WAIT(NSTG - 1);
        __syncthreads();

#pragma unroll
        for (int ks = 0; ks < 4; ++ks) {
            const int c0 = ks * 2;
            uint32_t afr[2][4];
#pragma unroll
            for (int mi = 0; mi < 2; ++mi) {
                uint32_t ad = aS + ((arow + mi * 16) << 7)
                            + ((uint32_t)((c0 + ach) ^ lrow) << 4);
                LDSM4(afr[mi][0], afr[mi][1], afr[mi][2], afr[mi][3], ad);
            }
            uint32_t bfr[8][2];
#pragma unroll
            for (int j = 0; j < 4; ++j) {
                uint32_t bd = bS + ((bnrow0 + j * 16) << 7)
                            + ((uint32_t)((c0 + bch) ^ lrow) << 4);
                LDSM4(bfr[2 * j][0], bfr[2 * j][1],
                      bfr[2 * j + 1][0], bfr[2 * j + 1][1], bd);
            }
#pragma unroll
            for (int mi = 0; mi < 2; ++mi)
#pragma unroll
                for (int nf = 0; nf < 8; ++nf)
                    MMA_TF32(acc[mi][nf], afr[mi], bfr[nf]);
        }
        __syncthreads();
        if (c + NSTG < NC)
            load_chunk(c + NSTG, aS, tid, NC1, A1, sA1, A2, B1, K1, B2, rb, cb);
    }

    // ---- Fused LSTM epilogue ---------------------------------------------
    const int kq = lane & 3;
    const int rA = lane >> 2;
    const int jgbase = (blockIdx.x * 2 + wn) * 16;
#pragma unroll
    for (int mi = 0; mi < 2; ++mi) {
#pragma unroll
        for (int ri = 0; ri < 2; ++ri) {
            const int row = rb + wm * 32 + mi * 16 + rA + ri * 8;
#pragma unroll
            for (int h = 0; h < 2; ++h) {
                const int jl = h * 8 + kq * 2;
                const size_t gidx = (size_t)row * H_SZ + jgbase + jl;
                float2 cold = *reinterpret_cast<const float2*>(&cst[gidx]);
                float cn2[2], hn2[2];
#pragma unroll
                for (int e = 0; e < 2; ++e) {
                    const int bofs = wn * 64 + h * 8 + kq * 2 + e;
                    float gi = acc[mi][0 * 2 + h][ri * 2 + e] + s_bias[bofs];
                    float gf = acc[mi][1 * 2 + h][ri * 2 + e] + s_bias[bofs + 16];
                    float gc = acc[mi][2 * 2 + h][ri * 2 + e] + s_bias[bofs + 32];
                    float go = acc[mi][3 * 2 + h][ri * 2 + e] + s_bias[bofs + 48];
                    gi = 1.f / (1.f + __expf(-gi));
                    gf = 1.f / (1.f + __expf(-gf));
                    go = 1.f / (1.f + __expf(-go));
                    gc = fmaxf(gc, 0.f);
                    float co = (e == 0) ? cold.x : cold.y;
                    float cn = gf * co + gi * gc;
                    cn2[e] = cn;
                    hn2[e] = to_tf32f(go * fmaxf(cn, 0.f));
                }
                *reinterpret_cast<float2*>(&cst[gidx])  = make_float2(cn2[0], cn2[1]);
                *reinterpret_cast<float2*>(&hout[gidx]) = make_float2(hn2[0], hn2[1]);
            }
        }
    }
}

// ---------------------------------------------------------------------------
// Final dense: out[b] = h2[b,:] @ Wd + bd
// ---------------------------------------------------------------------------
__global__ void dense_kernel(const float* __restrict__ Wd,
                             const float* __restrict__ bd,
                             float* __restrict__ out)
{
    const int row  = blockIdx.x * 8 + (threadIdx.x >> 5);
    const int lane = threadIdx.x & 31;
    const float* h2 = g_h2[(T_SZ - 1) & 1];
    float s = 0.f;
#pragma unroll
    for (int j = lane; j < H_SZ; j += 32)
        s += h2[(size_t)row * H_SZ + j] * Wd[j];
#pragma unroll
    for (int o = 16; o; o >>= 1) s += __shfl_xor_sync(0xFFFFFFFFu, s, o);
    if (lane == 0) out[row] = s + bd[0];
}

// ---------------------------------------------------------------------------
extern "C" void kernel_launch(void* const* d_in, const int* in_sizes, int n_in,
                              void* d_out, int out_size)
{
    const float* x  = (const float*)d_in[0];
    const float* W1 = (const float*)d_in[1];
    const float* U1 = (const float*)d_in[2];
    const float* b1 = (const float*)d_in[3];
    const float* W2 = (const float*)d_in[4];
    const float* U2 = (const float*)d_in[5];
    const float* b2 = (const float*)d_in[6];
    const float* Wd = (const float*)d_in[7];
    const float* bd = (const float*)d_in[8];
    float* out = (float*)d_out;
    (void)in_sizes; (void)n_in; (void)out_size;

    cudaFuncSetAttribute(lstm_step_mma<1>,
                         cudaFuncAttributeMaxDynamicSharedMemorySize, SMEM_DYN);
    cudaFuncSetAttribute(lstm_step_mma<2>,
                         cudaFuncAttributeMaxDynamicSharedMemorySize, SMEM_DYN);

    init_state_kernel<<<(B_SZ * H_SZ + 255) / 256, 256>>>();
    convert_x<<<B_SZ * T_SZ * F_SZ / 256, 256>>>(x);
    transpose_wu<<<2048 * 64 / 256, 256>>>(W1, 64, 0);
    transpose_wu<<<2048 * 512 / 256, 256>>>(U1, 512, 1);
    transpose_wu<<<2048 * 512 / 256, 256>>>(W2, 512, 2);
    transpose_wu<<<2048 * 512 / 256, 256>>>(U2, 512, 3);
    permute_bias<<<8, 256>>>(b1, 0);
    permute_bias<<<8, 256>>>(b2, 1);

    dim3 grid(16, 16);   // (N tiles, M tiles)
    for (int t = 0; t < T_SZ; ++t) {
        lstm_step_mma<1><<<grid, 256, SMEM_DYN>>>(t);
        lstm_step_mma<2><<<grid, 256, SMEM_DYN>>>(t);
    }

    dense_kernel<<<B_SZ / 8, 256>>>(Wd, bd, out);
}

// round 6
// speedup vs baseline: 5.5703x; 1.7916x over previous
#include <cuda_runtime.h>
#include <cuda_fp16.h>
#include <cstdint>
#include <math.h>

#define B_SZ 2048
#define T_SZ 128
#define F_SZ 64
#define H_SZ 512
#define NSTG 3
#define KC   64                               // k-elements (halves) per chunk
#define STAGE_BYTES (2 * 128 * 128)           // A(16KB) + B(16KB), fp16
#define SMEM_DYN (NSTG * STAGE_BYTES)         // 96 KB

// ---------------------------------------------------------------------------
// Device scratch. h state lives in fp16 (feeds MMAs + final dense only);
// c state stays fp32.
// ---------------------------------------------------------------------------
__device__ __align__(128) __half g_h1[2][B_SZ * H_SZ];
__device__ __align__(128) float  g_c1[B_SZ * H_SZ];
__device__ __align__(128) __half g_h2[2][B_SZ * H_SZ];
__device__ __align__(128) float  g_c2[B_SZ * H_SZ];
__device__ __align__(128) __half g_x16[B_SZ * T_SZ * F_SZ];
// Pre-transposed, gate-permuted fp16 weights, n-major: dst[n][k].
// permuted n -> gate g=(n>>4)&3, j=(n>>6)*16+(n&15); orig col = g*512 + j
__device__ __align__(128) __half g_Wt1[2048 * 64];
__device__ __align__(128) __half g_Ut1[2048 * 512];
__device__ __align__(128) __half g_Wt2[2048 * 512];
__device__ __align__(128) __half g_Ut2[2048 * 512];
__device__ __align__(128) float  g_bp1[2048];
__device__ __align__(128) float  g_bp2[2048];

// ---------------------------------------------------------------------------
// Helpers
// ---------------------------------------------------------------------------
__device__ __forceinline__ uint32_t smem_u32(const void* p) {
    uint32_t a;
    asm("{ .reg .u64 t; cvta.to.shared.u64 t, %1; cvt.u32.u64 %0, t; }" : "=r"(a) : "l"(p));
    return a;
}

#define CP_ASYNC16(dst, src) \
    asm volatile("cp.async.cg.shared.global [%0], [%1], 16;" :: "r"(dst), "l"(src) : "memory")
#define CP_ASYNC_COMMIT() asm volatile("cp.async.commit_group;" ::: "memory")
#define CP_ASYNC_WAIT(n)  asm volatile("cp.async.wait_group %0;" :: "n"(n) : "memory")

#define LDSM4(r0, r1, r2, r3, addr)                                           \
    asm volatile("ldmatrix.sync.aligned.m8n8.x4.shared.b16 {%0,%1,%2,%3}, [%4];" \
        : "=r"(r0), "=r"(r1), "=r"(r2), "=r"(r3) : "r"(addr))

#define MMA_F16(c, a, b)                                                      \
    asm volatile("mma.sync.aligned.m16n8k16.row.col.f32.f16.f16.f32 "         \
        "{%0,%1,%2,%3}, {%4,%5,%6,%7}, {%8,%9}, {%0,%1,%2,%3};"               \
        : "+f"((c)[0]), "+f"((c)[1]), "+f"((c)[2]), "+f"((c)[3])              \
        : "r"((a)[0]), "r"((a)[1]), "r"((a)[2]), "r"((a)[3]),                 \
          "r"((b)[0]), "r"((b)[1]))

// ---------------------------------------------------------------------------
// Init / prep kernels
// ---------------------------------------------------------------------------
__global__ void init_state_kernel() {
    int idx = blockIdx.x * blockDim.x + threadIdx.x;
    if (idx < B_SZ * H_SZ) {
        g_h1[1][idx] = __float2half(0.f);
        g_h2[1][idx] = __float2half(0.f);
        g_c1[idx] = 0.f; g_c2[idx] = 0.f;
    }
}

__global__ void convert_x(const float* __restrict__ x) {
    int idx = blockIdx.x * 256 + threadIdx.x;   // exact grid
    g_x16[idx] = __float2half(x[idx]);
}

__global__ void transpose_wu(const float* __restrict__ src, int K, int which) {
    __half* dst = (which == 0) ? g_Wt1 : (which == 1) ? g_Ut1
                : (which == 2) ? g_Wt2 : g_Ut2;
    int idx = blockIdx.x * 256 + threadIdx.x;   // exact grid: 2048*K
    int n = idx / K, k = idx - n * K;
    int orig = ((n >> 4) & 3) * 512 + (n >> 6) * 16 + (n & 15);
    dst[idx] = __float2half(src[(size_t)k * 2048 + orig]);
}

__global__ void permute_bias(const float* __restrict__ b, int which) {
    float* dst = (which == 0) ? g_bp1 : g_bp2;
    int n = blockIdx.x * 256 + threadIdx.x;
    dst[n] = b[((n >> 4) & 3) * 512 + (n >> 6) * 16 + (n & 15)];
}

// ---------------------------------------------------------------------------
// Stage loader: A[128 x 64] + B[128 x 64] fp16, 128B rows, XOR-swizzled
// ---------------------------------------------------------------------------
__device__ __forceinline__ void load_chunk(
    int c, uint32_t stBase, int tid, int NC1,
    const __half* __restrict__ A1, size_t sA1, const __half* __restrict__ A2,
    const __half* __restrict__ B1, int K1, const __half* __restrict__ B2,
    int rb, int cb)
{
    const __half* Asrc; size_t sA; const __half* Bsrc; int BK; int kloc;
    if (c < NC1) { Asrc = A1; sA = sA1;  Bsrc = B1; BK = K1;   kloc = c * KC; }
    else         { Asrc = A2; sA = H_SZ; Bsrc = B2; BK = H_SZ; kloc = (c - NC1) * KC; }

    const int r  = tid >> 1;            // 0..127
    const int cq = (tid & 1) * 4;       // 16B-chunk 0..3 or 4..7
    const uint32_t aS = stBase;
    const uint32_t bS = stBase + 16384;

    const __half* ag = Asrc + (size_t)(rb + r) * sA + kloc + cq * 8;
    const __half* bg = Bsrc + (size_t)(cb + r) * BK + kloc + cq * 8;
    const uint32_t rowoff = (uint32_t)r << 7;
#pragma unroll
    for (int q = 0; q < 4; ++q) {
        uint32_t sw = (uint32_t)((cq + q) ^ (r & 7)) << 4;
        CP_ASYNC16(aS + rowoff + sw, ag + q * 8);
        CP_ASYNC16(bS + rowoff + sw, bg + q * 8);
    }
    CP_ASYNC_COMMIT();
}

// ---------------------------------------------------------------------------
// Fused LSTM step: fp16 mma.sync GEMM [128x128 tile, K = K1+512] + gate math
// Grid (16 N-tiles, 16 M-tiles), 256 threads (8 warps of 32x64).
// ---------------------------------------------------------------------------
template <int LAYER>
__global__ void __launch_bounds__(256, 2)
lstm_step_mma(int t)
{
    extern __shared__ char dynraw[];
    __shared__ float s_bias[128];

    const int tid  = threadIdx.x;
    const int lane = tid & 31;
    const int warp = tid >> 5;
    const int wm   = warp >> 1;          // 0..3  (M)
    const int wn   = warp & 1;           // 0..1  (N)
    const int cur = t & 1, prev = cur ^ 1;
    const int rb = blockIdx.y * 128;
    const int cb = blockIdx.x * 128;

    constexpr int K1  = (LAYER == 1) ? F_SZ : H_SZ;
    constexpr int NC1 = K1 / KC;
    constexpr int NC  = NC1 + H_SZ / KC;

    const __half *A1, *A2, *B1, *B2; const float* bp;
    float *cst; __half *hout; size_t sA1;
    if (LAYER == 1) {
        A1 = g_x16 + (size_t)t * F_SZ; sA1 = (size_t)T_SZ * F_SZ;
        A2 = g_h1[prev]; B1 = g_Wt1; B2 = g_Ut1; bp = g_bp1;
        cst = g_c1; hout = g_h1[cur];
    } else {
        A1 = g_h1[cur]; sA1 = H_SZ;
        A2 = g_h2[prev]; B1 = g_Wt2; B2 = g_Ut2; bp = g_bp2;
        cst = g_c2; hout = g_h2[cur];
    }

    const uint32_t base = smem_u32(dynraw);
    if (tid < 128) s_bias[tid] = bp[cb + tid];

    float acc[2][8][4];
#pragma unroll
    for (int mi = 0; mi < 2; ++mi)
#pragma unroll
        for (int nf = 0; nf < 8; ++nf)
#pragma unroll
            for (int e = 0; e < 4; ++e) acc[mi][nf][e] = 0.f;

    // Prologue
#pragma unroll
    for (int c = 0; c < NSTG; ++c)
        load_chunk(c, base + c * STAGE_BYTES, tid, NC1, A1, sA1, A2, B1, K1, B2, rb, cb);

    // ldmatrix per-thread invariants (8-half 16B chunks)
    const int lrow = lane & 7;
    const int lm   = lane >> 3;           // matrix id 0..3
    const uint32_t arow = (uint32_t)(wm * 32 + (lm & 1) * 8 + lrow);
    const int      ach  = lm >> 1;
    const uint32_t bnrow0 = (uint32_t)(wn * 64 + (lm >> 1) * 8 + lrow);
    const int      bch    = lm & 1;

    for (int c = 0; c < NC; ++c) {
        const int s = (c % NSTG);
        const uint32_t aS = base + s * STAGE_BYTES;
        const uint32_t bS = aS + 16384;
        CP_ASYNC_WAIT(NSTG - 1);
        __syncthreads();

#pragma unroll
        for (int ks = 0; ks < 4; ++ks) {     // 4 x k16 = KC=64 halves
            const int c0 = ks * 2;
            uint32_t afr[2][4];
#pragma unroll
            for (int mi = 0; mi < 2; ++mi) {
                uint32_t ad = aS + ((arow + mi * 16) << 7)
                            + ((uint32_t)((c0 + ach) ^ lrow) << 4);
                LDSM4(afr[mi][0], afr[mi][1], afr[mi][2], afr[mi][3], ad);
            }
            uint32_t bfr[8][2];
#pragma unroll
            for (int j = 0; j < 4; ++j) {
                uint32_t bd = bS + ((bnrow0 + j * 16) << 7)
                            + ((uint32_t)((c0 + bch) ^ lrow) << 4);
                LDSM4(bfr[2 * j][0], bfr[2 * j][1],
                      bfr[2 * j + 1][0], bfr[2 * j + 1][1], bd);
            }
#pragma unroll
            for (int mi = 0; mi < 2; ++mi)
#pragma unroll
                for (int nf = 0; nf < 8; ++nf)
                    MMA_F16(acc[mi][nf], afr[mi], bfr[nf]);
        }
        __syncthreads();
        if (c + NSTG < NC)
            load_chunk(c + NSTG, aS, tid, NC1, A1, sA1, A2, B1, K1, B2, rb, cb);
    }

    // ---- Fused LSTM epilogue ---------------------------------------------
    const int kq = lane & 3;
    const int rA = lane >> 2;
    const int jgbase = (blockIdx.x * 2 + wn) * 16;
#pragma unroll
    for (int mi = 0; mi < 2; ++mi) {
#pragma unroll
        for (int ri = 0; ri < 2; ++ri) {
            const int row = rb + wm * 32 + mi * 16 + rA + ri * 8;
#pragma unroll
            for (int h = 0; h < 2; ++h) {
                const int jl = h * 8 + kq * 2;
                const size_t gidx = (size_t)row * H_SZ + jgbase + jl;
                float2 cold = *reinterpret_cast<const float2*>(&cst[gidx]);
                float cn2[2], hn2[2];
#pragma unroll
                for (int e = 0; e < 2; ++e) {
                    const int bofs = wn * 64 + h * 8 + kq * 2 + e;
                    float gi = acc[mi][0 * 2 + h][ri * 2 + e] + s_bias[bofs];
                    float gf = acc[mi][1 * 2 + h][ri * 2 + e] + s_bias[bofs + 16];
                    float gc = acc[mi][2 * 2 + h][ri * 2 + e] + s_bias[bofs + 32];
                    float go = acc[mi][3 * 2 + h][ri * 2 + e] + s_bias[bofs + 48];
                    gi = 1.f / (1.f + __expf(-gi));
                    gf = 1.f / (1.f + __expf(-gf));
                    go = 1.f / (1.f + __expf(-go));
                    gc = fmaxf(gc, 0.f);
                    float co = (e == 0) ? cold.x : cold.y;
                    float cn = gf * co + gi * gc;
                    cn2[e] = cn;
                    hn2[e] = go * fmaxf(cn, 0.f);
                }
                *reinterpret_cast<float2*>(&cst[gidx]) = make_float2(cn2[0], cn2[1]);
                *reinterpret_cast<__half2*>(&hout[gidx]) =
                    __floats2half2_rn(hn2[0], hn2[1]);
            }
        }
    }
}

// ---------------------------------------------------------------------------
// Final dense: out[b] = h2[b,:] @ Wd + bd
// ---------------------------------------------------------------------------
__global__ void dense_kernel(const float* __restrict__ Wd,
                             const float* __restrict__ bd,
                             float* __restrict__ out)
{
    const int row  = blockIdx.x * 8 + (threadIdx.x >> 5);
    const int lane = threadIdx.x & 31;
    const __half* h2 = g_h2[(T_SZ - 1) & 1];
    float s = 0.f;
#pragma unroll
    for (int j = lane; j < H_SZ; j += 32)
        s += __half2float(h2[(size_t)row * H_SZ + j]) * Wd[j];
#pragma unroll
    for (int o = 16; o; o >>= 1) s += __shfl_xor_sync(0xFFFFFFFFu, s, o);
    if (lane == 0) out[row] = s + bd[0];
}

// ---------------------------------------------------------------------------
extern "C" void kernel_launch(void* const* d_in, const int* in_sizes, int n_in,
                              void* d_out, int out_size)
{
    const float* x  = (const float*)d_in[0];
    const float* W1 = (const float*)d_in[1];
    const float* U1 = (const float*)d_in[2];
    const float* b1 = (const float*)d_in[3];
    const float* W2 = (const float*)d_in[4];
    const float* U2 = (const float*)d_in[5];
    const float* b2 = (const float*)d_in[6];
    const float* Wd = (const float*)d_in[7];
    const float* bd = (const float*)d_in[8];
    float* out = (float*)d_out;
    (void)in_sizes; (void)n_in; (void)out_size;

    cudaFuncSetAttribute(lstm_step_mma<1>,
                         cudaFuncAttributeMaxDynamicSharedMemorySize, SMEM_DYN);
    cudaFuncSetAttribute(lstm_step_mma<2>,
                         cudaFuncAttributeMaxDynamicSharedMemorySize, SMEM_DYN);

    init_state_kernel<<<(B_SZ * H_SZ + 255) / 256, 256>>>();
    convert_x<<<B_SZ * T_SZ * F_SZ / 256, 256>>>(x);
    transpose_wu<<<2048 * 64 / 256, 256>>>(W1, 64, 0);
    transpose_wu<<<2048 * 512 / 256, 256>>>(U1, 512, 1);
    transpose_wu<<<2048 * 512 / 256, 256>>>(W2, 512, 2);
    transpose_wu<<<2048 * 512 / 256, 256>>>(U2, 512, 3);
    permute_bias<<<8, 256>>>(b1, 0);
    permute_bias<<<8, 256>>>(b2, 1);

    dim3 grid(16, 16);   // (N tiles, M tiles)
    for (int t = 0; t < T_SZ; ++t) {
        lstm_step_mma<1><<<grid, 256, SMEM_DYN>>>(t);
        lstm_step_mma<2><<<grid, 256, SMEM_DYN>>>(t);
    }

    dense_kernel<<<B_SZ / 8, 256>>>(Wd, bd, out);
}

// round 7
// speedup vs baseline: 5.6466x; 1.0137x over previous
#include <cuda_runtime.h>
#include <cuda_fp16.h>
#include <cstdint>
#include <math.h>

#define B_SZ 2048
#define T_SZ 128
#define F_SZ 64
#define H_SZ 512
#define NSTG 3
#define KC   64                               // k halves per chunk
#define STAGE_BYTES (2 * 128 * 128)           // A(16KB) + B(16KB) fp16
#define SMEM_DYN (NSTG * STAGE_BYTES)         // 96 KB
#define NCTA 256

// ---------------------------------------------------------------------------
// Device scratch
// ---------------------------------------------------------------------------
__device__ __align__(128) __half g_h1[2][B_SZ * H_SZ];
__device__ __align__(128) float  g_c1[B_SZ * H_SZ];
__device__ __align__(128) __half g_h2[2][B_SZ * H_SZ];
__device__ __align__(128) float  g_c2[B_SZ * H_SZ];
__device__ __align__(128) __half g_x16[B_SZ * T_SZ * F_SZ];
// Pre-transposed, gate-permuted fp16 weights, n-major: dst[n][k].
// permuted n -> gate g=(n>>4)&3, j=(n>>6)*16+(n&15); orig col = g*512 + j
__device__ __align__(128) __half g_Wt1[2048 * 64];
__device__ __align__(128) __half g_Ut1[2048 * 512];
__device__ __align__(128) __half g_Wt2[2048 * 512];
__device__ __align__(128) __half g_Ut2[2048 * 512];
__device__ __align__(128) float  g_bp1[2048];
__device__ __align__(128) float  g_bp2[2048];
// Grid barrier state (reset by init kernel each launch/replay)
__device__ unsigned g_arrive;
__device__ unsigned g_epoch;

// ---------------------------------------------------------------------------
// Helpers
// ---------------------------------------------------------------------------
__device__ __forceinline__ uint32_t smem_u32(const void* p) {
    uint32_t a;
    asm("{ .reg .u64 t; cvta.to.shared.u64 t, %1; cvt.u32.u64 %0, t; }" : "=r"(a) : "l"(p));
    return a;
}

#define CP_ASYNC16(dst, src) \
    asm volatile("cp.async.cg.shared.global [%0], [%1], 16;" :: "r"(dst), "l"(src) : "memory")
#define CP_ASYNC_COMMIT() asm volatile("cp.async.commit_group;" ::: "memory")
#define CP_ASYNC_WAIT(n)  asm volatile("cp.async.wait_group %0;" :: "n"(n) : "memory")

#define LDSM4(r0, r1, r2, r3, addr)                                           \
    asm volatile("ldmatrix.sync.aligned.m8n8.x4.shared.b16 {%0,%1,%2,%3}, [%4];" \
        : "=r"(r0), "=r"(r1), "=r"(r2), "=r"(r3) : "r"(addr))

#define MMA_F16(c, a, b)                                                      \
    asm volatile("mma.sync.aligned.m16n8k16.row.col.f32.f16.f16.f32 "         \
        "{%0,%1,%2,%3}, {%4,%5,%6,%7}, {%8,%9}, {%0,%1,%2,%3};"               \
        : "+f"((c)[0]), "+f"((c)[1]), "+f"((c)[2]), "+f"((c)[3])              \
        : "r"((a)[0]), "r"((a)[1]), "r"((a)[2]), "r"((a)[3]),                 \
          "r"((b)[0]), "r"((b)[1]))

__device__ __forceinline__ unsigned ld_acq(const unsigned* p) {
    unsigned v;
    asm volatile("ld.acquire.gpu.u32 %0, [%1];" : "=r"(v) : "l"(p));
    return v;
}

// Monotonic-epoch grid barrier. Safe: all NCTA CTAs are co-resident
// (256 CTAs at 2 CTA/SM over 148 SMs).
__device__ __forceinline__ void grid_bar(unsigned target) {
    __syncthreads();
    if (threadIdx.x == 0) {
        __threadfence();
        unsigned a = atomicAdd(&g_arrive, 1u);
        if (a == NCTA - 1) {
            g_arrive = 0;
            __threadfence();
            atomicAdd(&g_epoch, 1u);
        } else {
            while (ld_acq(&g_epoch) < target) __nanosleep(64);
        }
    }
    __syncthreads();
}

// ---------------------------------------------------------------------------
// Init / prep kernels
// ---------------------------------------------------------------------------
__global__ void init_state_kernel() {
    int idx = blockIdx.x * blockDim.x + threadIdx.x;
    if (idx == 0) { g_arrive = 0; g_epoch = 0; }
    if (idx < B_SZ * H_SZ) {
        g_h1[1][idx] = __float2half(0.f);
        g_h2[1][idx] = __float2half(0.f);
        g_c1[idx] = 0.f; g_c2[idx] = 0.f;
    }
}

__global__ void convert_x(const float* __restrict__ x) {
    int idx = blockIdx.x * 256 + threadIdx.x;   // exact grid
    g_x16[idx] = __float2half(x[idx]);
}

__global__ void transpose_wu(const float* __restrict__ src, int K, int which) {
    __half* dst = (which == 0) ? g_Wt1 : (which == 1) ? g_Ut1
                : (which == 2) ? g_Wt2 : g_Ut2;
    int idx = blockIdx.x * 256 + threadIdx.x;   // exact grid: 2048*K
    int n = idx / K, k = idx - n * K;
    int orig = ((n >> 4) & 3) * 512 + (n >> 6) * 16 + (n & 15);
    dst[idx] = __float2half(src[(size_t)k * 2048 + orig]);
}

__global__ void permute_bias(const float* __restrict__ b, int which) {
    float* dst = (which == 0) ? g_bp1 : g_bp2;
    int n = blockIdx.x * 256 + threadIdx.x;
    dst[n] = b[((n >> 4) & 3) * 512 + (n >> 6) * 16 + (n & 15)];
}

// ---------------------------------------------------------------------------
// Stage loader: A[128 x 64] + B[128 x 64] fp16, 128B rows, XOR-swizzled
// ---------------------------------------------------------------------------
__device__ __forceinline__ void load_chunk(
    int c, uint32_t stBase, int tid, int NC1,
    const __half* __restrict__ A1, size_t sA1, const __half* __restrict__ A2,
    const __half* __restrict__ B1, int BK1, const __half* __restrict__ B2,
    int rb, int cb)
{
    const __half* Asrc; size_t sA; const __half* Bsrc; int BK; int kloc;
    if (c < NC1) { Asrc = A1; sA = sA1;  Bsrc = B1; BK = BK1;  kloc = c * KC; }
    else         { Asrc = A2; sA = H_SZ; Bsrc = B2; BK = H_SZ; kloc = (c - NC1) * KC; }

    const int r  = tid >> 1;            // 0..127
    const int cq = (tid & 1) * 4;       // 16B-chunk 0..3 or 4..7
    const uint32_t aS = stBase;
    const uint32_t bS = stBase + 16384;

    const __half* ag = Asrc + (size_t)(rb + r) * sA + kloc + cq * 8;
    const __half* bg = Bsrc + (size_t)(cb + r) * BK + kloc + cq * 8;
    const uint32_t rowoff = (uint32_t)r << 7;
#pragma unroll
    for (int q = 0; q < 4; ++q) {
        uint32_t sw = (uint32_t)((cq + q) ^ (r & 7)) << 4;
        CP_ASYNC16(aS + rowoff + sw, ag + q * 8);
        CP_ASYNC16(bS + rowoff + sw, bg + q * 8);
    }
    CP_ASYNC_COMMIT();
}

// ---------------------------------------------------------------------------
// One fused LSTM tile task: GEMM [128 x 128, K = NC1*64 + 512] + gate math.
// Runs inside the persistent kernel; owns the CTA's smem ring for its duration.
// ---------------------------------------------------------------------------
__device__ void run_tile(
    const __half* __restrict__ A1, size_t sA1, int NC1,
    const __half* __restrict__ A2,
    const __half* __restrict__ B1, int BK1,
    const __half* __restrict__ B2,
    const float* __restrict__ sbias,
    float* __restrict__ cst, __half* __restrict__ hout,
    int rb, int cbI, uint32_t base, int tid)
{
    const int NC   = NC1 + H_SZ / KC;
    const int cb   = cbI * 128;
    const int lane = tid & 31;
    const int warp = tid >> 5;
    const int wm   = warp >> 1;          // 0..3  (M)
    const int wn   = warp & 1;           // 0..1  (N)

    float acc[2][8][4];
#pragma unroll
    for (int mi = 0; mi < 2; ++mi)
#pragma unroll
        for (int nf = 0; nf < 8; ++nf)
#pragma unroll
            for (int e = 0; e < 4; ++e) acc[mi][nf][e] = 0.f;

    // Prologue: fill stages
#pragma unroll
    for (int c = 0; c < NSTG; ++c)
        load_chunk(c, base + c * STAGE_BYTES, tid, NC1, A1, sA1, A2, B1, BK1, B2, rb, cb);

    // ldmatrix per-thread invariants
    const int lrow = lane & 7;
    const int lm   = lane >> 3;
    const uint32_t arow   = (uint32_t)(wm * 32 + (lm & 1) * 8 + lrow);
    const int      ach    = lm >> 1;
    const uint32_t bnrow0 = (uint32_t)(wn * 64 + (lm >> 1) * 8 + lrow);
    const int      bch    = lm & 1;

    for (int c = 0; c < NC; ++c) {
        const uint32_t aS = base + (c % NSTG) * STAGE_BYTES;
        const uint32_t bS = aS + 16384;
        // Tail-correct wait: guarantee group for chunk c has completed.
        const int rem = NC - 1 - c;
        if (rem >= 2)      CP_ASYNC_WAIT(2);
        else if (rem == 1) CP_ASYNC_WAIT(1);
        else               CP_ASYNC_WAIT(0);
        __syncthreads();

#pragma unroll
        for (int ks = 0; ks < 4; ++ks) {     // 4 x k16 = 64 halves
            const int c0 = ks * 2;
            uint32_t afr[2][4];
#pragma unroll
            for (int mi = 0; mi < 2; ++mi) {
                uint32_t ad = aS + ((arow + mi * 16) << 7)
                            + ((uint32_t)((c0 + ach) ^ lrow) << 4);
                LDSM4(afr[mi][0], afr[mi][1], afr[mi][2], afr[mi][3], ad);
            }
            uint32_t bfr[8][2];
#pragma unroll
            for (int j = 0; j < 4; ++j) {
                uint32_t bd = bS + ((bnrow0 + j * 16) << 7)
                            + ((uint32_t)((c0 + bch) ^ lrow) << 4);
                LDSM4(bfr[2 * j][0], bfr[2 * j][1],
                      bfr[2 * j + 1][0], bfr[2 * j + 1][1], bd);
            }
#pragma unroll
            for (int mi = 0; mi < 2; ++mi)
#pragma unroll
                for (int nf = 0; nf < 8; ++nf)
                    MMA_F16(acc[mi][nf], afr[mi], bfr[nf]);
        }
        __syncthreads();
        if (c + NSTG < NC)
            load_chunk(c + NSTG, aS, tid, NC1, A1, sA1, A2, B1, BK1, B2, rb, cb);
    }

    // ---- LSTM epilogue ----------------------------------------------------
    const int kq = lane & 3;
    const int rA = lane >> 2;
    const int jgbase = (cbI * 2 + wn) * 16;
#pragma unroll
    for (int mi = 0; mi < 2; ++mi) {
#pragma unroll
        for (int ri = 0; ri < 2; ++ri) {
            const int row = rb + wm * 32 + mi * 16 + rA + ri * 8;
#pragma unroll
            for (int h = 0; h < 2; ++h) {
                const int jl = h * 8 + kq * 2;
                const size_t gidx = (size_t)row * H_SZ + jgbase + jl;
                float2 cold = *reinterpret_cast<const float2*>(&cst[gidx]);
                float cn2[2], hn2[2];
#pragma unroll
                for (int e = 0; e < 2; ++e) {
                    const int bofs = wn * 64 + h * 8 + kq * 2 + e;
                    float gi = acc[mi][0 * 2 + h][ri * 2 + e] + sbias[bofs];
                    float gf = acc[mi][1 * 2 + h][ri * 2 + e] + sbias[bofs + 16];
                    float gc = acc[mi][2 * 2 + h][ri * 2 + e] + sbias[bofs + 32];
                    float go = acc[mi][3 * 2 + h][ri * 2 + e] + sbias[bofs + 48];
                    gi = 1.f / (1.f + __expf(-gi));
                    gf = 1.f / (1.f + __expf(-gf));
                    go = 1.f / (1.f + __expf(-go));
                    gc = fmaxf(gc, 0.f);
                    float co = (e == 0) ? cold.x : cold.y;
                    float cn = gf * co + gi * gc;
                    cn2[e] = cn;
                    hn2[e] = go * fmaxf(cn, 0.f);
                }
                *reinterpret_cast<float2*>(&cst[gidx]) = make_float2(cn2[0], cn2[1]);
                *reinterpret_cast<__half2*>(&hout[gidx]) =
                    __floats2half2_rn(hn2[0], hn2[1]);
            }
        }
    }
}

// ---------------------------------------------------------------------------
// Persistent kernel: interval k runs {L2(k-1), L1(k)} then one grid barrier.
// 129 barriers replace 258 kernel launches. Dense folded in at the end.
// ---------------------------------------------------------------------------
__global__ void __launch_bounds__(256, 2)
lstm_persistent(const float* __restrict__ Wd,
                const float* __restrict__ bd,
                float* __restrict__ out)
{
    extern __shared__ char dynraw[];
    __shared__ float s_b1[128], s_b2[128];

    const int tid = threadIdx.x;
    const int bid = blockIdx.x;
    const int cbI = bid & 15;
    const int rb  = (bid >> 4) * 128;
    const uint32_t base = smem_u32(dynraw);

    if (tid < 128) {
        s_b1[tid] = g_bp1[cbI * 128 + tid];
        s_b2[tid] = g_bp2[cbI * 128 + tid];
    }
    __syncthreads();

    for (int k = 0; k <= T_SZ; ++k) {
        if (k >= 1) {                      // layer 2 at t = k-1
            const int t = k - 1;
            run_tile(g_h1[t & 1], H_SZ, H_SZ / KC,
                     g_h2[(t & 1) ^ 1],
                     g_Wt2, H_SZ, g_Ut2,
                     s_b2, g_c2, g_h2[t & 1],
                     rb, cbI, base, tid);
        }
        if (k <= T_SZ - 1) {               // layer 1 at t = k
            const int t = k;
            run_tile(g_x16 + (size_t)t * F_SZ, (size_t)T_SZ * F_SZ, F_SZ / KC,
                     g_h1[(t & 1) ^ 1],
                     g_Wt1, F_SZ, g_Ut1,
                     s_b1, g_c1, g_h1[t & 1],
                     rb, cbI, base, tid);
        }
        grid_bar((unsigned)(k + 1));
    }

    // ---- Final dense: rows [bid*8, bid*8+8), one warp per row ------------
    const int lane = tid & 31;
    const int row  = bid * 8 + (tid >> 5);
    const __half* h2 = g_h2[(T_SZ - 1) & 1];
    float s = 0.f;
#pragma unroll
    for (int j = lane; j < H_SZ; j += 32)
        s += __half2float(h2[(size_t)row * H_SZ + j]) * Wd[j];
#pragma unroll
    for (int o = 16; o; o >>= 1) s += __shfl_xor_sync(0xFFFFFFFFu, s, o);
    if (lane == 0) out[row] = s + bd[0];
}

// ---------------------------------------------------------------------------
extern "C" void kernel_launch(void* const* d_in, const int* in_sizes, int n_in,
                              void* d_out, int out_size)
{
    const float* x  = (const float*)d_in[0];
    const float* W1 = (const float*)d_in[1];
    const float* U1 = (const float*)d_in[2];
    const float* b1 = (const float*)d_in[3];
    const float* W2 = (const float*)d_in[4];
    const float* U2 = (const float*)d_in[5];
    const float* b2 = (const float*)d_in[6];
    const float* Wd = (const float*)d_in[7];
    const float* bd = (const float*)d_in[8];
    float* out = (float*)d_out;
    (void)in_sizes; (void)n_in; (void)out_size;

    cudaFuncSetAttribute(lstm_persistent,
                         cudaFuncAttributeMaxDynamicSharedMemorySize, SMEM_DYN);

    init_state_kernel<<<(B_SZ * H_SZ + 255) / 256, 256>>>();
    convert_x<<<B_SZ * T_SZ * F_SZ / 256, 256>>>(x);
    transpose_wu<<<2048 * 64 / 256, 256>>>(W1, 64, 0);
    transpose_wu<<<2048 * 512 / 256, 256>>>(U1, 512, 1);
    transpose_wu<<<2048 * 512 / 256, 256>>>(W2, 512, 2);
    transpose_wu<<<2048 * 512 / 256, 256>>>(U2, 512, 3);
    permute_bias<<<8, 256>>>(b1, 0);
    permute_bias<<<8, 256>>>(b2, 1);

    lstm_persistent<<<NCTA, 256, SMEM_DYN>>>(Wd, bd, out);
}

// round 8
// speedup vs baseline: 5.8320x; 1.0328x over previous
#include <cuda_runtime.h>
#include <cuda_fp16.h>
#include <cstdint>
#include <math.h>

#define B_SZ 2048
#define T_SZ 128
#define F_SZ 64
#define H_SZ 512
#define NSTG 3
#define KC   64                               // k halves per chunk
#define STAGE_BYTES (2 * 128 * 128)           // A(16KB) + B(16KB) fp16
#define SMEM_DYN (NSTG * STAGE_BYTES)         // 96 KB
#define NCTA 256
#define NGRP 16
#define GSTR 32                               // barrier stride (128B)

// ---------------------------------------------------------------------------
// Device scratch
// ---------------------------------------------------------------------------
__device__ __align__(128) __half g_h1[2][B_SZ * H_SZ];
__device__ __align__(128) float  g_c1[B_SZ * H_SZ];
__device__ __align__(128) __half g_h2[2][B_SZ * H_SZ];
__device__ __align__(128) float  g_c2[B_SZ * H_SZ];
__device__ __align__(128) __half g_x16[B_SZ * T_SZ * F_SZ];
// Pre-transposed, gate-permuted fp16 weights, n-major: dst[n][k].
// permuted n -> gate g=(n>>4)&3, j=(n>>6)*16+(n&15); orig col = g*512 + j
__device__ __align__(128) __half g_Wt1[2048 * 64];
__device__ __align__(128) __half g_Ut1[2048 * 512];
__device__ __align__(128) __half g_Wt2[2048 * 512];
__device__ __align__(128) __half g_Ut2[2048 * 512];
__device__ __align__(128) float  g_bp1[2048];
__device__ __align__(128) float  g_bp2[2048];
// Per-row-group barrier state (reset by init kernel each launch/replay)
__device__ unsigned g_garr[NGRP * GSTR];
__device__ unsigned g_gep[NGRP * GSTR];

// ---------------------------------------------------------------------------
// Helpers
// ---------------------------------------------------------------------------
__device__ __forceinline__ uint32_t smem_u32(const void* p) {
    uint32_t a;
    asm("{ .reg .u64 t; cvta.to.shared.u64 t, %1; cvt.u32.u64 %0, t; }" : "=r"(a) : "l"(p));
    return a;
}

#define CP_ASYNC16(dst, src) \
    asm volatile("cp.async.cg.shared.global [%0], [%1], 16;" :: "r"(dst), "l"(src) : "memory")
#define CP_ASYNC_COMMIT() asm volatile("cp.async.commit_group;" ::: "memory")
#define CP_ASYNC_WAIT(n)  asm volatile("cp.async.wait_group %0;" :: "n"(n) : "memory")

#define LDSM4(r0, r1, r2, r3, addr)                                           \
    asm volatile("ldmatrix.sync.aligned.m8n8.x4.shared.b16 {%0,%1,%2,%3}, [%4];" \
        : "=r"(r0), "=r"(r1), "=r"(r2), "=r"(r3) : "r"(addr))

#define MMA_F16(c, a, b)                                                      \
    asm volatile("mma.sync.aligned.m16n8k16.row.col.f32.f16.f16.f32 "         \
        "{%0,%1,%2,%3}, {%4,%5,%6,%7}, {%8,%9}, {%0,%1,%2,%3};"               \
        : "+f"((c)[0]), "+f"((c)[1]), "+f"((c)[2]), "+f"((c)[3])              \
        : "r"((a)[0]), "r"((a)[1]), "r"((a)[2]), "r"((a)[3]),                 \
          "r"((b)[0]), "r"((b)[1]))

__device__ __forceinline__ unsigned ld_acq(const unsigned* p) {
    unsigned v;
    asm volatile("ld.acquire.gpu.u32 %0, [%1];" : "=r"(v) : "l"(p));
    return v;
}

// Row-group barrier: 16 CTAs sharing the same batch-row block. Safe: all
// NCTA CTAs are co-resident (256 <= 2/SM * 148).
__device__ __forceinline__ void group_bar(int gI, unsigned target) {
    __syncthreads();
    if (threadIdx.x == 0) {
        __threadfence();
        unsigned a = atomicAdd(&g_garr[gI * GSTR], 1u);
        if (a == 15u) {
            g_garr[gI * GSTR] = 0u;
            __threadfence();
            atomicAdd(&g_gep[gI * GSTR], 1u);
        } else {
            while (ld_acq(&g_gep[gI * GSTR]) < target) __nanosleep(32);
        }
    }
    __syncthreads();
}

// ---------------------------------------------------------------------------
// Init / prep kernels
// ---------------------------------------------------------------------------
__global__ void init_state_kernel() {
    int idx = blockIdx.x * blockDim.x + threadIdx.x;
    if (idx < NGRP * GSTR) { g_garr[idx] = 0u; g_gep[idx] = 0u; }
    if (idx < B_SZ * H_SZ) {
        g_h1[1][idx] = __float2half(0.f);
        g_h2[1][idx] = __float2half(0.f);
        g_c1[idx] = 0.f; g_c2[idx] = 0.f;
    }
}

__global__ void convert_x(const float* __restrict__ x) {
    int idx = blockIdx.x * 256 + threadIdx.x;   // exact grid
    g_x16[idx] = __float2half(x[idx]);
}

__global__ void transpose_wu(const float* __restrict__ src, int K, int which) {
    __half* dst = (which == 0) ? g_Wt1 : (which == 1) ? g_Ut1
                : (which == 2) ? g_Wt2 : g_Ut2;
    int idx = blockIdx.x * 256 + threadIdx.x;   // exact grid: 2048*K
    int n = idx / K, k = idx - n * K;
    int orig = ((n >> 4) & 3) * 512 + (n >> 6) * 16 + (n & 15);
    dst[idx] = __float2half(src[(size_t)k * 2048 + orig]);
}

__global__ void permute_bias(const float* __restrict__ b, int which) {
    float* dst = (which == 0) ? g_bp1 : g_bp2;
    int n = blockIdx.x * 256 + threadIdx.x;
    dst[n] = b[((n >> 4) & 3) * 512 + (n >> 6) * 16 + (n & 15)];
}

// ---------------------------------------------------------------------------
// Tile descriptor + chunk loader
// ---------------------------------------------------------------------------
struct Tile {
    const __half* A1; const __half* A2;
    const __half* B1; const __half* B2;
    unsigned sA1;          // A1 row stride in halves
    int NC1; int BK1;      // chunks in first K-segment; B1 row stride
    const float* sbias;
    float* cst; __half* hout;
};

__device__ __forceinline__ void load_chunk_t(
    const Tile& T, int c, uint32_t stBase, int tid, int rb, int cb)
{
    const __half* Asrc; unsigned sA; const __half* Bsrc; int BK; int kloc;
    if (c < T.NC1) { Asrc = T.A1; sA = T.sA1; Bsrc = T.B1; BK = T.BK1; kloc = c * KC; }
    else           { Asrc = T.A2; sA = H_SZ;  Bsrc = T.B2; BK = H_SZ;  kloc = (c - T.NC1) * KC; }

    const int r  = tid >> 1;            // 0..127
    const int cq = (tid & 1) * 4;       // 16B-chunk 0..3 or 4..7
    const uint32_t aS = stBase;
    const uint32_t bS = stBase + 16384;

    const __half* ag = Asrc + (size_t)(rb + r) * sA + kloc + cq * 8;
    const __half* bg = Bsrc + (size_t)(cb + r) * BK + kloc + cq * 8;
    const uint32_t rowoff = (uint32_t)r << 7;
#pragma unroll
    for (int q = 0; q < 4; ++q) {
        uint32_t sw = (uint32_t)((cq + q) ^ (r & 7)) << 4;
        CP_ASYNC16(aS + rowoff + sw, ag + q * 8);
        CP_ASYNC16(bS + rowoff + sw, bg + q * 8);
    }
    CP_ASYNC_COMMIT();
}

// ---------------------------------------------------------------------------
// Consume one tile from the continuous per-interval chunk stream.
// Schedule per chunk: wait(chunk ready) -> sync -> issue chunk gc+2 -> compute.
// Single __syncthreads per chunk; overwrite-safety: stage (gc+2)%3 was
// consumed at iteration gc-1, and this iteration's sync proves all warps
// finished it.
// ---------------------------------------------------------------------------
template <typename F>
__device__ void consume_tile(
    const Tile& T, int gcBase, int NC, int ntot, F&& issue,
    uint32_t base, int tid, int rb, int cbI)
{
    const int lane = tid & 31;
    const int warp = tid >> 5;
    const int wm   = warp >> 1;
    const int wn   = warp & 1;

    float acc[2][8][4];
#pragma unroll
    for (int mi = 0; mi < 2; ++mi)
#pragma unroll
        for (int nf = 0; nf < 8; ++nf)
#pragma unroll
            for (int e = 0; e < 4; ++e) acc[mi][nf][e] = 0.f;

    const int lrow = lane & 7;
    const int lm   = lane >> 3;
    const uint32_t arow   = (uint32_t)(wm * 32 + (lm & 1) * 8 + lrow);
    const int      ach    = lm >> 1;
    const uint32_t bnrow0 = (uint32_t)(wn * 64 + (lm >> 1) * 8 + lrow);
    const int      bch    = lm & 1;

    for (int c = 0; c < NC; ++c) {
        const int gc = gcBase + c;
        // wait: groups complete in order; after this, chunk gc is resident.
        if (gc == ntot - 1) CP_ASYNC_WAIT(0);
        else                CP_ASYNC_WAIT(1);
        __syncthreads();
        issue(gc + 2);

        const uint32_t aS = base + (gc % NSTG) * STAGE_BYTES;
        const uint32_t bS = aS + 16384;
#pragma unroll
        for (int ks = 0; ks < 4; ++ks) {
            const int c0 = ks * 2;
            uint32_t afr[2][4];
#pragma unroll
            for (int mi = 0; mi < 2; ++mi) {
                uint32_t ad = aS + ((arow + mi * 16) << 7)
                            + ((uint32_t)((c0 + ach) ^ lrow) << 4);
                LDSM4(afr[mi][0], afr[mi][1], afr[mi][2], afr[mi][3], ad);
            }
            uint32_t bfr[8][2];
#pragma unroll
            for (int j = 0; j < 4; ++j) {
                uint32_t bd = bS + ((bnrow0 + j * 16) << 7)
                            + ((uint32_t)((c0 + bch) ^ lrow) << 4);
                LDSM4(bfr[2 * j][0], bfr[2 * j][1],
                      bfr[2 * j + 1][0], bfr[2 * j + 1][1], bd);
            }
#pragma unroll
            for (int mi = 0; mi < 2; ++mi)
#pragma unroll
                for (int nf = 0; nf < 8; ++nf)
                    MMA_F16(acc[mi][nf], afr[mi], bfr[nf]);
        }
    }

    // ---- LSTM epilogue (overlaps with next tile's in-flight loads) --------
    const int kq = lane & 3;
    const int rA = lane >> 2;
    const int jgbase = (cbI * 2 + wn) * 16;
#pragma unroll
    for (int mi = 0; mi < 2; ++mi) {
#pragma unroll
        for (int ri = 0; ri < 2; ++ri) {
            const int row = rb + wm * 32 + mi * 16 + rA + ri * 8;
#pragma unroll
            for (int h = 0; h < 2; ++h) {
                const int jl = h * 8 + kq * 2;
                const size_t gidx = (size_t)row * H_SZ + jgbase + jl;
                float2 cold = *reinterpret_cast<const float2*>(&T.cst[gidx]);
                float cn2[2], hn2[2];
#pragma unroll
                for (int e = 0; e < 2; ++e) {
                    const int bofs = wn * 64 + h * 8 + kq * 2 + e;
                    float gi = acc[mi][0 * 2 + h][ri * 2 + e] + T.sbias[bofs];
                    float gf = acc[mi][1 * 2 + h][ri * 2 + e] + T.sbias[bofs + 16];
                    float gc2 = acc[mi][2 * 2 + h][ri * 2 + e] + T.sbias[bofs + 32];
                    float go = acc[mi][3 * 2 + h][ri * 2 + e] + T.sbias[bofs + 48];
                    gi = 1.f / (1.f + __expf(-gi));
                    gf = 1.f / (1.f + __expf(-gf));
                    go = 1.f / (1.f + __expf(-go));
                    gc2 = fmaxf(gc2, 0.f);
                    float co = (e == 0) ? cold.x : cold.y;
                    float cn = gf * co + gi * gc2;
                    cn2[e] = cn;
                    hn2[e] = go * fmaxf(cn, 0.f);
                }
                *reinterpret_cast<float2*>(&T.cst[gidx]) = make_float2(cn2[0], cn2[1]);
                *reinterpret_cast<__half2*>(&T.hout[gidx]) =
                    __floats2half2_rn(hn2[0], hn2[1]);
            }
        }
    }
}

// ---------------------------------------------------------------------------
// Persistent kernel. Interval k runs the continuous stream
// {L2(k-1): 16 chunks, L1(k): 9 chunks} then one ROW-GROUP barrier.
// ---------------------------------------------------------------------------
__global__ void __launch_bounds__(256, 2)
lstm_persistent(const float* __restrict__ Wd,
                const float* __restrict__ bd,
                float* __restrict__ out)
{
    extern __shared__ char dynraw[];
    __shared__ float s_b1[128], s_b2[128];

    const int tid = threadIdx.x;
    const int bid = blockIdx.x;
    const int cbI = bid & 15;
    const int gI  = bid >> 4;
    const int rb  = gI * 128;
    const int cb  = cbI * 128;
    const uint32_t base = smem_u32(dynraw);

    if (tid < 128) {
        s_b1[tid] = g_bp1[cbI * 128 + tid];
        s_b2[tid] = g_bp2[cbI * 128 + tid];
    }
    __syncthreads();

    for (int k = 0; k <= T_SZ; ++k) {
        const int n0 = (k >= 1) ? 16 : 0;           // L2 tile at t = k-1
        const int n1 = (k <= T_SZ - 1) ? 9 : 0;     // L1 tile at t = k
        const int ntot = n0 + n1;
        const int t0 = (k >= 1) ? (k - 1) : 0;
        const int t1 = (k <= T_SZ - 1) ? k : 0;

        Tile T0;
        T0.A1 = g_h1[t0 & 1];            T0.sA1 = H_SZ;
        T0.A2 = g_h2[(t0 & 1) ^ 1];
        T0.B1 = g_Wt2;  T0.BK1 = H_SZ;   T0.B2 = g_Ut2;
        T0.NC1 = H_SZ / KC;
        T0.sbias = s_b2; T0.cst = g_c2;  T0.hout = g_h2[t0 & 1];

        Tile T1;
        T1.A1 = g_x16 + (size_t)t1 * F_SZ; T1.sA1 = T_SZ * F_SZ;
        T1.A2 = g_h1[(t1 & 1) ^ 1];
        T1.B1 = g_Wt1;  T1.BK1 = F_SZ;   T1.B2 = g_Ut1;
        T1.NC1 = F_SZ / KC;
        T1.sbias = s_b1; T1.cst = g_c1;  T1.hout = g_h1[t1 & 1];

        auto issue = [&](int j) {
            if (j >= ntot) return;
            const uint32_t st = base + (j % NSTG) * STAGE_BYTES;
            if (j < n0) load_chunk_t(T0, j,      st, tid, rb, cb);
            else        load_chunk_t(T1, j - n0, st, tid, rb, cb);
        };

        // interval prologue: two chunks in flight
        issue(0);
        issue(1);

        if (n0) consume_tile(T0, 0,  16, ntot, issue, base, tid, rb, cbI);
        if (n1) consume_tile(T1, n0,  9, ntot, issue, base, tid, rb, cbI);

        group_bar(gI, (unsigned)(k + 1));
    }

    // ---- Final dense: 8 group-local rows, one warp per row ---------------
    const int lane = tid & 31;
    const int row  = rb + cbI * 8 + (tid >> 5);
    const __half* h2 = g_h2[(T_SZ - 1) & 1];
    float s = 0.f;
#pragma unroll
    for (int j = lane; j < H_SZ; j += 32)
        s += __half2float(h2[(size_t)row * H_SZ + j]) * Wd[j];
#pragma unroll
    for (int o = 16; o; o >>= 1) s += __shfl_xor_sync(0xFFFFFFFFu, s, o);
    if (lane == 0) out[row] = s + bd[0];
}

// ---------------------------------------------------------------------------
extern "C" void kernel_launch(void* const* d_in, const int* in_sizes, int n_in,
                              void* d_out, int out_size)
{
    const float* x  = (const float*)d_in[0];
    const float* W1 = (const float*)d_in[1];
    const float* U1 = (const float*)d_in[2];
    const float* b1 = (const float*)d_in[3];
    const float* W2 = (const float*)d_in[4];
    const float* U2 = (const float*)d_in[5];
    const float* b2 = (const float*)d_in[6];
    const float* Wd = (const float*)d_in[7];
    const float* bd = (const float*)d_in[8];
    float* out = (float*)d_out;
    (void)in_sizes; (void)n_in; (void)out_size;

    cudaFuncSetAttribute(lstm_persistent,
                         cudaFuncAttributeMaxDynamicSharedMemorySize, SMEM_DYN);

    init_state_kernel<<<(B_SZ * H_SZ + 255) / 256, 256>>>();
    convert_x<<<B_SZ * T_SZ * F_SZ / 256, 256>>>(x);
    transpose_wu<<<2048 * 64 / 256, 256>>>(W1, 64, 0);
    transpose_wu<<<2048 * 512 / 256, 256>>>(U1, 512, 1);
    transpose_wu<<<2048 * 512 / 256, 256>>>(W2, 512, 2);
    transpose_wu<<<2048 * 512 / 256, 256>>>(U2, 512, 3);
    permute_bias<<<8, 256>>>(b1, 0);
    permute_bias<<<8, 256>>>(b2, 1);

    lstm_persistent<<<NCTA, 256, SMEM_DYN>>>(Wd, bd, out);
}

// round 9
// speedup vs baseline: 5.8373x; 1.0009x over previous
#include <cuda_runtime.h>
#include <cuda_fp16.h>
#include <cstdint>
#include <math.h>

#define B_SZ 2048
#define T_SZ 128
#define F_SZ 64
#define H_SZ 512
#define NSTG 3
#define KC   64                               // k halves per chunk
#define STAGE_BYTES (2 * 128 * 128)           // A(16KB) + B(16KB) fp16
#define SMEM_DYN (NSTG * STAGE_BYTES)         // 96 KB
#define NCTA 256
#define NGRP 16
#define GSTR 32                               // barrier stride (128B)

// ---------------------------------------------------------------------------
// Device scratch
// ---------------------------------------------------------------------------
__device__ __align__(128) __half g_h1[2][B_SZ * H_SZ];
__device__ __align__(128) float  g_c1[B_SZ * H_SZ];
__device__ __align__(128) __half g_h2[2][B_SZ * H_SZ];
__device__ __align__(128) float  g_c2[B_SZ * H_SZ];
__device__ __align__(128) __half g_x16[B_SZ * T_SZ * F_SZ];
// Pre-transposed, gate-permuted fp16 weights, n-major: dst[n][k].
// permuted n -> gate g=(n>>4)&3, j=(n>>6)*16+(n&15); orig col = g*512 + j
__device__ __align__(128) __half g_Wt1[2048 * 64];
__device__ __align__(128) __half g_Ut1[2048 * 512];
__device__ __align__(128) __half g_Wt2[2048 * 512];
__device__ __align__(128) __half g_Ut2[2048 * 512];
__device__ __align__(128) float  g_bp1[2048];
__device__ __align__(128) float  g_bp2[2048];
// Per-row-group barrier state (reset by init kernel each launch/replay)
__device__ unsigned g_garr[NGRP * GSTR];
__device__ unsigned g_gep[NGRP * GSTR];

// ---------------------------------------------------------------------------
// Helpers
// ---------------------------------------------------------------------------
__device__ __forceinline__ uint32_t smem_u32(const void* p) {
    uint32_t a;
    asm("{ .reg .u64 t; cvta.to.shared.u64 t, %1; cvt.u32.u64 %0, t; }" : "=r"(a) : "l"(p));
    return a;
}

#define CP_ASYNC16(dst, src) \
    asm volatile("cp.async.cg.shared.global [%0], [%1], 16;" :: "r"(dst), "l"(src) : "memory")
#define CP_ASYNC_COMMIT() asm volatile("cp.async.commit_group;" ::: "memory")
#define CP_ASYNC_WAIT(n)  asm volatile("cp.async.wait_group %0;" :: "n"(n) : "memory")

#define LDSM4(r0, r1, r2, r3, addr)                                           \
    asm volatile("ldmatrix.sync.aligned.m8n8.x4.shared.b16 {%0,%1,%2,%3}, [%4];" \
        : "=r"(r0), "=r"(r1), "=r"(r2), "=r"(r3) : "r"(addr))

#define MMA_F16(c, a, b)                                                      \
    asm volatile("mma.sync.aligned.m16n8k16.row.col.f32.f16.f16.f32 "         \
        "{%0,%1,%2,%3}, {%4,%5,%6,%7}, {%8,%9}, {%0,%1,%2,%3};"               \
        : "+f"((c)[0]), "+f"((c)[1]), "+f"((c)[2]), "+f"((c)[3])              \
        : "r"((a)[0]), "r"((a)[1]), "r"((a)[2]), "r"((a)[3]),                 \
          "r"((b)[0]), "r"((b)[1]))

__device__ __forceinline__ unsigned ld_acq(const unsigned* p) {
    unsigned v;
    asm volatile("ld.acquire.gpu.u32 %0, [%1];" : "=r"(v) : "l"(p));
    return v;
}

// Row-group barrier: 16 CTAs sharing the same batch-row block. Safe: all
// NCTA CTAs are co-resident (256 <= 2/SM * 148).
__device__ __forceinline__ void group_bar(int gI, unsigned target) {
    __syncthreads();
    if (threadIdx.x == 0) {
        __threadfence();
        unsigned a = atomicAdd(&g_garr[gI * GSTR], 1u);
        if (a == 15u) {
            g_garr[gI * GSTR] = 0u;
            __threadfence();
            atomicAdd(&g_gep[gI * GSTR], 1u);
        } else {
            while (ld_acq(&g_gep[gI * GSTR]) < target) __nanosleep(32);
        }
    }
    __syncthreads();
}

// ---------------------------------------------------------------------------
// Init / prep kernels
// ---------------------------------------------------------------------------
__global__ void init_state_kernel() {
    int idx = blockIdx.x * blockDim.x + threadIdx.x;
    if (idx < NGRP * GSTR) { g_garr[idx] = 0u; g_gep[idx] = 0u; }
    if (idx < B_SZ * H_SZ) {
        g_h1[1][idx] = __float2half(0.f);
        g_h2[1][idx] = __float2half(0.f);
        g_c1[idx] = 0.f; g_c2[idx] = 0.f;
    }
}

__global__ void convert_x(const float* __restrict__ x) {
    int idx = blockIdx.x * 256 + threadIdx.x;   // exact grid
    g_x16[idx] = __float2half(x[idx]);
}

__global__ void transpose_wu(const float* __restrict__ src, int K, int which) {
    __half* dst = (which == 0) ? g_Wt1 : (which == 1) ? g_Ut1
                : (which == 2) ? g_Wt2 : g_Ut2;
    int idx = blockIdx.x * 256 + threadIdx.x;   // exact grid: 2048*K
    int n = idx / K, k = idx - n * K;
    int orig = ((n >> 4) & 3) * 512 + (n >> 6) * 16 + (n & 15);
    dst[idx] = __float2half(src[(size_t)k * 2048 + orig]);
}

__global__ void permute_bias(const float* __restrict__ b, int which) {
    float* dst = (which == 0) ? g_bp1 : g_bp2;
    int n = blockIdx.x * 256 + threadIdx.x;
    dst[n] = b[((n >> 4) & 3) * 512 + (n >> 6) * 16 + (n & 15)];
}

// ---------------------------------------------------------------------------
// Tile descriptor + chunk loader
// ---------------------------------------------------------------------------
struct Tile {
    const __half* A1; const __half* A2;
    const __half* B1; const __half* B2;
    unsigned sA1;          // A1 row stride in halves
    int NC1; int BK1;      // chunks in first K-segment; B1 row stride
    const float* sbias;
    float* cst; __half* hout;
};

__device__ __forceinline__ void load_chunk_t(
    const Tile& T, int c, uint32_t stBase, int tid, int rb, int cb)
{
    const __half* Asrc; unsigned sA; const __half* Bsrc; int BK; int kloc;
    if (c < T.NC1) { Asrc = T.A1; sA = T.sA1; Bsrc = T.B1; BK = T.BK1; kloc = c * KC; }
    else           { Asrc = T.A2; sA = H_SZ;  Bsrc = T.B2; BK = H_SZ;  kloc = (c - T.NC1) * KC; }

    const int r  = tid >> 1;            // 0..127
    const int cq = (tid & 1) * 4;       // 16B-chunk 0..3 or 4..7
    const uint32_t aS = stBase;
    const uint32_t bS = stBase + 16384;

    const __half* ag = Asrc + (size_t)(rb + r) * sA + kloc + cq * 8;
    const __half* bg = Bsrc + (size_t)(cb + r) * BK + kloc + cq * 8;
    const uint32_t rowoff = (uint32_t)r << 7;
#pragma unroll
    for (int q = 0; q < 4; ++q) {
        uint32_t sw = (uint32_t)((cq + q) ^ (r & 7)) << 4;
        CP_ASYNC16(aS + rowoff + sw, ag + q * 8);
        CP_ASYNC16(bS + rowoff + sw, bg + q * 8);
    }
    CP_ASYNC_COMMIT();
}

// ---------------------------------------------------------------------------
// Consume one tile from the continuous per-interval chunk stream.
// Schedule per chunk: wait(chunk ready) -> sync -> issue chunk gc+2 -> compute.
// Single __syncthreads per chunk; overwrite-safety: stage (gc+2)%3 was
// consumed at iteration gc-1, and this iteration's sync proves all warps
// finished it.
// ---------------------------------------------------------------------------
template <typename F>
__device__ void consume_tile(
    const Tile& T, int gcBase, int NC, int ntot, F&& issue,
    uint32_t base, int tid, int rb, int cbI)
{
    const int lane = tid & 31;
    const int warp = tid >> 5;
    const int wm   = warp >> 1;
    const int wn   = warp & 1;

    float acc[2][8][4];
#pragma unroll
    for (int mi = 0; mi < 2; ++mi)
#pragma unroll
        for (int nf = 0; nf < 8; ++nf)
#pragma unroll
            for (int e = 0; e < 4; ++e) acc[mi][nf][e] = 0.f;

    const int lrow = lane & 7;
    const int lm   = lane >> 3;
    const uint32_t arow   = (uint32_t)(wm * 32 + (lm & 1) * 8 + lrow);
    const int      ach    = lm >> 1;
    const uint32_t bnrow0 = (uint32_t)(wn * 64 + (lm >> 1) * 8 + lrow);
    const int      bch    = lm & 1;

    for (int c = 0; c < NC; ++c) {
        const int gc = gcBase + c;
        // wait: groups complete in order; after this, chunk gc is resident.
        if (gc == ntot - 1) CP_ASYNC_WAIT(0);
        else                CP_ASYNC_WAIT(1);
        __syncthreads();
        issue(gc + 2);

        const uint32_t aS = base + (gc % NSTG) * STAGE_BYTES;
        const uint32_t bS = aS + 16384;
#pragma unroll
        for (int ks = 0; ks < 4; ++ks) {
            const int c0 = ks * 2;
            uint32_t afr[2][4];
#pragma unroll
            for (int mi = 0; mi < 2; ++mi) {
                uint32_t ad = aS + ((arow + mi * 16) << 7)
                            + ((uint32_t)((c0 + ach) ^ lrow) << 4);
                LDSM4(afr[mi][0], afr[mi][1], afr[mi][2], afr[mi][3], ad);
            }
            uint32_t bfr[8][2];
#pragma unroll
            for (int j = 0; j < 4; ++j) {
                uint32_t bd = bS + ((bnrow0 + j * 16) << 7)
                            + ((uint32_t)((c0 + bch) ^ lrow) << 4);
                LDSM4(bfr[2 * j][0], bfr[2 * j][1],
                      bfr[2 * j + 1][0], bfr[2 * j + 1][1], bd);
            }
#pragma unroll
            for (int mi = 0; mi < 2; ++mi)
#pragma unroll
                for (int nf = 0; nf < 8; ++nf)
                    MMA_F16(acc[mi][nf], afr[mi], bfr[nf]);
        }
    }

    // ---- LSTM epilogue (overlaps with next tile's in-flight loads) --------
    const int kq = lane & 3;
    const int rA = lane >> 2;
    const int jgbase = (cbI * 2 + wn) * 16;
#pragma unroll
    for (int mi = 0; mi < 2; ++mi) {
#pragma unroll
        for (int ri = 0; ri < 2; ++ri) {
            const int row = rb + wm * 32 + mi * 16 + rA + ri * 8;
#pragma unroll
            for (int h = 0; h < 2; ++h) {
                const int jl = h * 8 + kq * 2;
                const size_t gidx = (size_t)row * H_SZ + jgbase + jl;
                float2 cold = *reinterpret_cast<const float2*>(&T.cst[gidx]);
                float cn2[2], hn2[2];
#pragma unroll
                for (int e = 0; e < 2; ++e) {
                    const int bofs = wn * 64 + h * 8 + kq * 2 + e;
                    float gi = acc[mi][0 * 2 + h][ri * 2 + e] + T.sbias[bofs];
                    float gf = acc[mi][1 * 2 + h][ri * 2 + e] + T.sbias[bofs + 16];
                    float gc2 = acc[mi][2 * 2 + h][ri * 2 + e] + T.sbias[bofs + 32];
                    float go = acc[mi][3 * 2 + h][ri * 2 + e] + T.sbias[bofs + 48];
                    gi = 1.f / (1.f + __expf(-gi));
                    gf = 1.f / (1.f + __expf(-gf));
                    go = 1.f / (1.f + __expf(-go));
                    gc2 = fmaxf(gc2, 0.f);
                    float co = (e == 0) ? cold.x : cold.y;
                    float cn = gf * co + gi * gc2;
                    cn2[e] = cn;
                    hn2[e] = go * fmaxf(cn, 0.f);
                }
                *reinterpret_cast<float2*>(&T.cst[gidx]) = make_float2(cn2[0], cn2[1]);
                *reinterpret_cast<__half2*>(&T.hout[gidx]) =
                    __floats2half2_rn(hn2[0], hn2[1]);
            }
        }
    }
}

// ---------------------------------------------------------------------------
// Persistent kernel. Interval k runs the continuous stream
// {L2(k-1): 16 chunks, L1(k): 9 chunks} then one ROW-GROUP barrier.
// ---------------------------------------------------------------------------
__global__ void __launch_bounds__(256, 2)
lstm_persistent(const float* __restrict__ Wd,
                const float* __restrict__ bd,
                float* __restrict__ out)
{
    extern __shared__ char dynraw[];
    __shared__ float s_b1[128], s_b2[128];

    const int tid = threadIdx.x;
    const int bid = blockIdx.x;
    const int cbI = bid & 15;
    const int gI  = bid >> 4;
    const int rb  = gI * 128;
    const int cb  = cbI * 128;
    const uint32_t base = smem_u32(dynraw);

    if (tid < 128) {
        s_b1[tid] = g_bp1[cbI * 128 + tid];
        s_b2[tid] = g_bp2[cbI * 128 + tid];
    }
    __syncthreads();

    for (int k = 0; k <= T_SZ; ++k) {
        const int n0 = (k >= 1) ? 16 : 0;           // L2 tile at t = k-1
        const int n1 = (k <= T_SZ - 1) ? 9 : 0;     // L1 tile at t = k
        const int ntot = n0 + n1;
        const int t0 = (k >= 1) ? (k - 1) : 0;
        const int t1 = (k <= T_SZ - 1) ? k : 0;

        Tile T0;
        T0.A1 = g_h1[t0 & 1];            T0.sA1 = H_SZ;
        T0.A2 = g_h2[(t0 & 1) ^ 1];
        T0.B1 = g_Wt2;  T0.BK1 = H_SZ;   T0.B2 = g_Ut2;
        T0.NC1 = H_SZ / KC;
        T0.sbias = s_b2; T0.cst = g_c2;  T0.hout = g_h2[t0 & 1];

        Tile T1;
        T1.A1 = g_x16 + (size_t)t1 * F_SZ; T1.sA1 = T_SZ * F_SZ;
        T1.A2 = g_h1[(t1 & 1) ^ 1];
        T1.B1 = g_Wt1;  T1.BK1 = F_SZ;   T1.B2 = g_Ut1;
        T1.NC1 = F_SZ / KC;
        T1.sbias = s_b1; T1.cst = g_c1;  T1.hout = g_h1[t1 & 1];

        auto issue = [&](int j) {
            if (j >= ntot) return;
            const uint32_t st = base + (j % NSTG) * STAGE_BYTES;
            if (j < n0) load_chunk_t(T0, j,      st, tid, rb, cb);
            else        load_chunk_t(T1, j - n0, st, tid, rb, cb);
        };

        // interval prologue: two chunks in flight
        issue(0);
        issue(1);

        if (n0) consume_tile(T0, 0,  16, ntot, issue, base, tid, rb, cbI);
        if (n1) consume_tile(T1, n0,  9, ntot, issue, base, tid, rb, cbI);

        group_bar(gI, (unsigned)(k + 1));
    }

    // ---- Final dense: 8 group-local rows, one warp per row ---------------
    const int lane = tid & 31;
    const int row  = rb + cbI * 8 + (tid >> 5);
    const __half* h2 = g_h2[(T_SZ - 1) & 1];
    float s = 0.f;
#pragma unroll
    for (int j = lane; j < H_SZ; j += 32)
        s += __half2float(h2[(size_t)row * H_SZ + j]) * Wd[j];
#pragma unroll
    for (int o = 16; o; o >>= 1) s += __shfl_xor_sync(0xFFFFFFFFu, s, o);
    if (lane == 0) out[row] = s + bd[0];
}

// ---------------------------------------------------------------------------
extern "C" void kernel_launch(void* const* d_in, const int* in_sizes, int n_in,
                              void* d_out, int out_size)
{
    const float* x  = (const float*)d_in[0];
    const float* W1 = (const float*)d_in[1];
    const float* U1 = (const float*)d_in[2];
    const float* b1 = (const float*)d_in[3];
    const float* W2 = (const float*)d_in[4];
    const float* U2 = (const float*)d_in[5];
    const float* b2 = (const float*)d_in[6];
    const float* Wd = (const float*)d_in[7];
    const float* bd = (const float*)d_in[8];
    float* out = (float*)d_out;
    (void)in_sizes; (void)n_in; (void)out_size;

    cudaFuncSetAttribute(lstm_persistent,
                         cudaFuncAttributeMaxDynamicSharedMemorySize, SMEM_DYN);

    init_state_kernel<<<(B_SZ * H_SZ + 255) / 256, 256>>>();
    convert_x<<<B_SZ * T_SZ * F_SZ / 256, 256>>>(x);
    transpose_wu<<<2048 * 64 / 256, 256>>>(W1, 64, 0);
    transpose_wu<<<2048 * 512 / 256, 256>>>(U1, 512, 1);
    transpose_wu<<<2048 * 512 / 256, 256>>>(W2, 512, 2);
    transpose_wu<<<2048 * 512 / 256, 256>>>(U2, 512, 3);
    permute_bias<<<8, 256>>>(b1, 0);
    permute_bias<<<8, 256>>>(b2, 1);

    lstm_persistent<<<NCTA, 256, SMEM_DYN>>>(Wd, bd, out);
}